// round 1
// baseline (speedup 1.0000x reference)
#include <cuda_runtime.h>
#include <math.h>

#define L 1024
#define BATCH 8
#define E 512
#define NH 8
#define HD 64
#define BL (BATCH * L)
#define NUMC 10000

// ---------------- scratch (static device globals; no allocation) ----------------
__device__ float g_x[BL * E];
__device__ float g_qsh[BL * E];
__device__ float g_qp[BL * E];
__device__ float g_kp[BL * E];
__device__ float g_vp[BL * E];
__device__ float g_att[BL * E];
__device__ float g_proj[BL * E];   // also reused for ff2
__device__ float g_h[BL * E];
__device__ float g_ff1[BL * E];
__device__ float g_m[L];

// ---------------- helpers ----------------
__device__ __forceinline__ float blockSum128(float v, float* sh) {
    int lane = threadIdx.x & 31, w = threadIdx.x >> 5;
    #pragma unroll
    for (int o = 16; o > 0; o >>= 1) v += __shfl_xor_sync(0xffffffffu, v, o);
    if (lane == 0) sh[w] = v;
    __syncthreads();
    float r = sh[0] + sh[1] + sh[2] + sh[3];
    __syncthreads();
    return r;
}

// ---------------- embed: x = inter[q + 10000 r] + pos ; qsh = ex[qry] ----------------
__global__ void embed_kernel(const int* __restrict__ q, const int* __restrict__ r,
                             const int* __restrict__ qry,
                             const float* __restrict__ inter,
                             const float* __restrict__ ex,
                             const float* __restrict__ pos) {
    int t = blockIdx.x;                 // token 0..8191
    int l = t & (L - 1);
    int e4 = threadIdx.x;               // 0..127, one float4 each
    int rowx = q[t] + NUMC * r[t];
    float4 a = ((const float4*)inter)[rowx * (E / 4) + e4];
    float4 p = ((const float4*)pos)[l * (E / 4) + e4];
    float4 o = make_float4(a.x + p.x, a.y + p.y, a.z + p.z, a.w + p.w);
    ((float4*)g_x)[t * (E / 4) + e4] = o;
    ((float4*)g_qsh)[t * (E / 4) + e4] = ((const float4*)ex)[qry[t] * (E / 4) + e4];
}

// ---------------- mask: m[i] = argmax(alphas[i]+gumbel[i])==0 ; L1 = sum|alphas| ----------------
__global__ void mask_kernel(const float* __restrict__ alphas,
                            const float* __restrict__ gumbel,
                            float* __restrict__ out_l1) {
    int i = threadIdx.x;                // 1024 threads
    float a0 = alphas[2 * i], a1 = alphas[2 * i + 1];
    float z0 = a0 + gumbel[2 * i], z1 = a1 + gumbel[2 * i + 1];
    g_m[i] = (z0 >= z1) ? 1.0f : 0.0f;  // argmax ties -> first index
    float v = fabsf(a0) + fabsf(a1);
    __shared__ float sh[32];
    int lane = i & 31, w = i >> 5;
    #pragma unroll
    for (int o = 16; o > 0; o >>= 1) v += __shfl_xor_sync(0xffffffffu, v, o);
    if (lane == 0) sh[w] = v;
    __syncthreads();
    if (i < 32) {
        float x = sh[i];
        #pragma unroll
        for (int o = 16; o > 0; o >>= 1) x += __shfl_xor_sync(0xffffffffu, x, o);
        if (i == 0) out_l1[0] = x;
    }
}

// ---------------- SGEMM: C[M,N] = A[M,K] @ W[N,K]^T + bias, optional relu ----------------
// 128x128x8 tile, 256 threads, 8x8 per-thread microtile.
__global__ __launch_bounds__(256, 1)
void gemm_nt(const float* __restrict__ A, const float* __restrict__ W,
             const float* __restrict__ bias, float* __restrict__ C,
             int M, int N, int K, int relu) {
    __shared__ float As[8][128];
    __shared__ float Ws[8][128];
    int t = threadIdx.x;
    int m0 = blockIdx.y * 128;
    int n0 = blockIdx.x * 128;
    int tx = t & 15, ty = t >> 4;
    int lr = t >> 1;                    // 0..127
    int lc = (t & 1) * 4;               // 0 or 4
    const float* Ag = A + (size_t)(m0 + lr) * K + lc;
    const float* Wg = W + (size_t)(n0 + lr) * K + lc;

    float acc[8][8];
    #pragma unroll
    for (int i = 0; i < 8; i++)
        #pragma unroll
        for (int j = 0; j < 8; j++) acc[i][j] = 0.f;

    for (int k0 = 0; k0 < K; k0 += 8) {
        float4 av = *(const float4*)(Ag + k0);
        float4 wv = *(const float4*)(Wg + k0);
        __syncthreads();
        As[lc + 0][lr] = av.x; As[lc + 1][lr] = av.y; As[lc + 2][lr] = av.z; As[lc + 3][lr] = av.w;
        Ws[lc + 0][lr] = wv.x; Ws[lc + 1][lr] = wv.y; Ws[lc + 2][lr] = wv.z; Ws[lc + 3][lr] = wv.w;
        __syncthreads();
        #pragma unroll
        for (int k = 0; k < 8; k++) {
            float a[8], b[8];
            #pragma unroll
            for (int i = 0; i < 4; i++) { a[i] = As[k][ty * 4 + i]; a[i + 4] = As[k][64 + ty * 4 + i]; }
            #pragma unroll
            for (int j = 0; j < 4; j++) { b[j] = Ws[k][tx * 4 + j]; b[j + 4] = Ws[k][64 + tx * 4 + j]; }
            #pragma unroll
            for (int i = 0; i < 8; i++)
                #pragma unroll
                for (int j = 0; j < 8; j++) acc[i][j] += a[i] * b[j];
        }
    }

    #pragma unroll
    for (int i = 0; i < 8; i++) {
        int r = m0 + ((i < 4) ? (ty * 4 + i) : (64 + ty * 4 + (i - 4)));
        #pragma unroll
        for (int j = 0; j < 8; j++) {
            int c = n0 + ((j < 4) ? (tx * 4 + j) : (64 + tx * 4 + (j - 4)));
            float v = acc[i][j] + bias[c];
            if (relu) v = fmaxf(v, 0.f);
            C[(size_t)r * N + c] = v;
        }
    }
}

// ---------------- fused masked-causal attention (online softmax) ----------------
// grid (B*NH, L/128), block 128; one thread = one query row.
__global__ __launch_bounds__(128, 1)
void attn_kernel(const float* __restrict__ qp, const float* __restrict__ kp,
                 const float* __restrict__ vp, float* __restrict__ out) {
    __shared__ float Ks[32][64];
    __shared__ float Vs[32][64];
    __shared__ float Ms[L];
    int bh = blockIdx.x;
    int b = bh >> 3, h = bh & 7;
    int t = threadIdx.x;
    int i = blockIdx.y * 128 + t;

    const float* qb = qp + ((size_t)(b * L + i)) * E + h * HD;
    float q[64];
    #pragma unroll
    for (int d4 = 0; d4 < 16; d4++) {
        float4 v = *(const float4*)(qb + d4 * 4);
        q[d4 * 4] = v.x; q[d4 * 4 + 1] = v.y; q[d4 * 4 + 2] = v.z; q[d4 * 4 + 3] = v.w;
    }
    #pragma unroll
    for (int c = 0; c < 8; c++) Ms[t + 128 * c] = g_m[t + 128 * c];

    float acc[64];
    #pragma unroll
    for (int d = 0; d < 64; d++) acc[d] = 0.f;
    float mx = -1e30f, sum = 0.f;

    int ntiles = (blockIdx.y + 1) * 4;
    for (int tile = 0; tile < ntiles; tile++) {
        int j0 = tile * 32;
        __syncthreads();
        #pragma unroll
        for (int c = 0; c < 4; c++) {
            int idx = t + 128 * c;          // float4 index 0..511
            int row = idx >> 4;
            int col = (idx & 15) * 4;
            size_t off = ((size_t)(b * L + j0 + row)) * E + h * HD + col;
            *(float4*)&Ks[row][col] = *(const float4*)(kp + off);
            *(float4*)&Vs[row][col] = *(const float4*)(vp + off);
        }
        __syncthreads();
        for (int jj = 0; jj < 32; jj++) {
            int j = j0 + jj;
            if (j > i) break;
            if (Ms[i - j] == 0.f) continue;
            float s = 0.f;
            #pragma unroll
            for (int d4 = 0; d4 < 16; d4++) {
                float4 kv = *(const float4*)&Ks[jj][d4 * 4];
                s += q[d4 * 4] * kv.x + q[d4 * 4 + 1] * kv.y
                   + q[d4 * 4 + 2] * kv.z + q[d4 * 4 + 3] * kv.w;
            }
            s *= 0.125f;  // 1/sqrt(64)
            if (s > mx) {
                float f = __expf(mx - s);
                sum *= f;
                #pragma unroll
                for (int d = 0; d < 64; d++) acc[d] *= f;
                mx = s;
            }
            float p = __expf(s - mx);
            sum += p;
            #pragma unroll
            for (int d4 = 0; d4 < 16; d4++) {
                float4 vv = *(const float4*)&Vs[jj][d4 * 4];
                acc[d4 * 4]     += p * vv.x;
                acc[d4 * 4 + 1] += p * vv.y;
                acc[d4 * 4 + 2] += p * vv.z;
                acc[d4 * 4 + 3] += p * vv.w;
            }
        }
    }
    float inv = 1.f / sum;
    float* ob = out + ((size_t)(b * L + i)) * E + h * HD;
    #pragma unroll
    for (int d4 = 0; d4 < 16; d4++) {
        float4 v = make_float4(acc[d4 * 4] * inv, acc[d4 * 4 + 1] * inv,
                               acc[d4 * 4 + 2] * inv, acc[d4 * 4 + 3] * inv);
        *(float4*)(ob + d4 * 4) = v;
    }
}

// ---------------- out = LayerNorm(a + b) * s + bb ----------------
__global__ void addln_kernel(const float* __restrict__ a, const float* __restrict__ b,
                             const float* __restrict__ s, const float* __restrict__ bb,
                             float* __restrict__ out) {
    int tkn = blockIdx.x;
    int t = threadIdx.x;    // 128 threads x float4
    __shared__ float sh[4];
    float4 av = ((const float4*)a)[tkn * 128 + t];
    float4 bv = ((const float4*)b)[tkn * 128 + t];
    float4 v = make_float4(av.x + bv.x, av.y + bv.y, av.z + bv.z, av.w + bv.w);
    float total = blockSum128(v.x + v.y + v.z + v.w, sh);
    float mean = total * (1.f / 512.f);
    float dx = v.x - mean, dy = v.y - mean, dz = v.z - mean, dw = v.w - mean;
    float vtot = blockSum128(dx * dx + dy * dy + dz * dz + dw * dw, sh);
    float inv = rsqrtf(vtot * (1.f / 512.f) + 1e-5f);
    float4 sv = ((const float4*)s)[t];
    float4 bv2 = ((const float4*)bb)[t];
    float4 o = make_float4(dx * inv * sv.x + bv2.x, dy * inv * sv.y + bv2.y,
                           dz * inv * sv.z + bv2.z, dw * inv * sv.w + bv2.w);
    ((float4*)out)[tkn * 128 + t] = o;
}

// ---------------- p = sigmoid(x . w + b) ----------------
__global__ void pred_kernel(const float* __restrict__ w, const float* __restrict__ pb,
                            float* __restrict__ out) {
    int tkn = blockIdx.x;
    int t = threadIdx.x;
    __shared__ float sh[4];
    float4 xv = ((const float4*)g_x)[tkn * 128 + t];
    float4 wv = ((const float4*)w)[t];
    float local = xv.x * wv.x + xv.y * wv.y + xv.z * wv.z + xv.w * wv.w;
    float z = blockSum128(local, sh) + pb[0];
    if (t == 0) out[tkn] = 1.f / (1.f + __expf(-z));
}

// ---------------- launch ----------------
extern "C" void kernel_launch(void* const* d_in, const int* in_sizes, int n_in,
                              void* d_out, int out_size) {
    const int*   q      = (const int*)d_in[0];
    const int*   r      = (const int*)d_in[1];
    const int*   qry    = (const int*)d_in[2];
    const float* alphas = (const float*)d_in[3];
    const float* gumbel = (const float*)d_in[4];
    const float* inter  = (const float*)d_in[5];
    const float* ex     = (const float*)d_in[6];
    const float* pos    = (const float*)d_in[7];
    const float* Wqkv   = (const float*)d_in[8];
    const float* bqkv   = (const float*)d_in[9];
    const float* Wo     = (const float*)d_in[10];
    const float* bo     = (const float*)d_in[11];
    const float* ln1_s  = (const float*)d_in[12];
    const float* ln1_b  = (const float*)d_in[13];
    const float* W1     = (const float*)d_in[14];
    const float* b1     = (const float*)d_in[15];
    const float* W2     = (const float*)d_in[16];
    const float* b2     = (const float*)d_in[17];
    const float* ln2_s  = (const float*)d_in[18];
    const float* ln2_b  = (const float*)d_in[19];
    const float* predw  = (const float*)d_in[20];
    const float* predb  = (const float*)d_in[21];
    float* out = (float*)d_out;

    float *px, *pqsh, *pqp, *pkp, *pvp, *patt, *pproj, *ph, *pff1;
    cudaGetSymbolAddress((void**)&px, g_x);
    cudaGetSymbolAddress((void**)&pqsh, g_qsh);
    cudaGetSymbolAddress((void**)&pqp, g_qp);
    cudaGetSymbolAddress((void**)&pkp, g_kp);
    cudaGetSymbolAddress((void**)&pvp, g_vp);
    cudaGetSymbolAddress((void**)&patt, g_att);
    cudaGetSymbolAddress((void**)&pproj, g_proj);
    cudaGetSymbolAddress((void**)&ph, g_h);
    cudaGetSymbolAddress((void**)&pff1, g_ff1);

    embed_kernel<<<BL, 128>>>(q, r, qry, inter, ex, pos);
    mask_kernel<<<1, 1024>>>(alphas, gumbel, out + BL);  // out[8192] = mask_L1

    dim3 ggrid(E / 128, BL / 128);   // (4, 64)
    dim3 agrid(BATCH * NH, L / 128); // (64, 8)

    for (int l = 0; l < 2; l++) {
        const float* Wl = Wqkv + (size_t)l * 3 * E * E;
        const float* bl = bqkv + (size_t)l * 3 * E;
        gemm_nt<<<ggrid, 256>>>(pqsh, Wl,             bl,           pqp, BL, E, E, 0);
        gemm_nt<<<ggrid, 256>>>(px,   Wl + E * E,     bl + E,       pkp, BL, E, E, 0);
        gemm_nt<<<ggrid, 256>>>(px,   Wl + 2 * E * E, bl + 2 * E,   pvp, BL, E, E, 0);
        attn_kernel<<<agrid, 128>>>(pqp, pkp, pvp, patt);
        gemm_nt<<<ggrid, 256>>>(patt, Wo + (size_t)l * E * E, bo + l * E, pproj, BL, E, E, 0);
        addln_kernel<<<BL, 128>>>(pqsh, pproj, ln1_s + l * E, ln1_b + l * E, ph);
        gemm_nt<<<ggrid, 256>>>(ph,   W1 + (size_t)l * E * E, b1 + l * E, pff1, BL, E, E, 1);
        gemm_nt<<<ggrid, 256>>>(pff1, W2 + (size_t)l * E * E, b2 + l * E, pproj, BL, E, E, 0);
        addln_kernel<<<BL, 128>>>(ph, pproj, ln2_s + l * E, ln2_b + l * E, px);
    }

    pred_kernel<<<BL, 128>>>(predw, predb, out);
}

// round 5
// speedup vs baseline: 1.5685x; 1.5685x over previous
#include <cuda_runtime.h>
#include <cuda_bf16.h>
#include <math.h>
#include <stdint.h>

#define L 1024
#define BATCH 8
#define E 512
#define NH 8
#define HD 64
#define BL (BATCH * L)
#define NUMC 10000
#define EE (E * E)

// ---------------- scratch (static device globals; no allocation) ----------------
__device__ float g_x[BL * E];
__device__ float g_qsh[BL * E];
__device__ float g_qp[BL * E];
__device__ float g_kv[BL * 2 * E];
__device__ float g_att[BL * E];
__device__ float g_proj[BL * E];
__device__ float g_h[BL * E];
__device__ float g_ff1[BL * E];
__device__ float g_m[L];

// bf16 split buffers
__device__ __nv_bfloat16 g_qh[BL * E], g_ql[BL * E];     // qsh split (persistent)
__device__ __nv_bfloat16 g_ah[BL * E], g_al[BL * E];     // generic activation split
__device__ __nv_bfloat16 g_wh[12 * EE], g_wl[12 * EE];   // all weights split

// ---------------- helpers ----------------
__device__ __forceinline__ float blockSum128(float v, float* sh) {
    int lane = threadIdx.x & 31, w = threadIdx.x >> 5;
    #pragma unroll
    for (int o = 16; o > 0; o >>= 1) v += __shfl_xor_sync(0xffffffffu, v, o);
    if (lane == 0) sh[w] = v;
    __syncthreads();
    float r = sh[0] + sh[1] + sh[2] + sh[3];
    __syncthreads();
    return r;
}

__device__ __forceinline__ uint32_t smem_u32(const void* p) {
    uint32_t a;
    asm("{ .reg .u64 t; cvta.to.shared.u64 t, %1; cvt.u32.u64 %0, t; }" : "=r"(a) : "l"(p));
    return a;
}

// ---------------- embed ----------------
__global__ void embed_kernel(const int* __restrict__ q, const int* __restrict__ r,
                             const int* __restrict__ qry,
                             const float* __restrict__ inter,
                             const float* __restrict__ ex,
                             const float* __restrict__ pos) {
    int t = blockIdx.x;
    int l = t & (L - 1);
    int e4 = threadIdx.x;
    int rowx = q[t] + NUMC * r[t];
    float4 a = ((const float4*)inter)[rowx * (E / 4) + e4];
    float4 p = ((const float4*)pos)[l * (E / 4) + e4];
    ((float4*)g_x)[t * (E / 4) + e4] = make_float4(a.x + p.x, a.y + p.y, a.z + p.z, a.w + p.w);
    ((float4*)g_qsh)[t * (E / 4) + e4] = ((const float4*)ex)[qry[t] * (E / 4) + e4];
}

// ---------------- mask ----------------
__global__ void mask_kernel(const float* __restrict__ alphas,
                            const float* __restrict__ gumbel,
                            float* __restrict__ out_l1) {
    int i = threadIdx.x;
    float a0 = alphas[2 * i], a1 = alphas[2 * i + 1];
    float z0 = a0 + gumbel[2 * i], z1 = a1 + gumbel[2 * i + 1];
    g_m[i] = (z0 >= z1) ? 1.0f : 0.0f;
    float v = fabsf(a0) + fabsf(a1);
    __shared__ float sh[32];
    int lane = i & 31, w = i >> 5;
    #pragma unroll
    for (int o = 16; o > 0; o >>= 1) v += __shfl_xor_sync(0xffffffffu, v, o);
    if (lane == 0) sh[w] = v;
    __syncthreads();
    if (i < 32) {
        float x = sh[i];
        #pragma unroll
        for (int o = 16; o > 0; o >>= 1) x += __shfl_xor_sync(0xffffffffu, x, o);
        if (i == 0) out_l1[0] = x;
    }
}

// ---------------- fp32 -> bf16 hi/lo split ----------------
__global__ void conv_split(const float* __restrict__ src,
                           __nv_bfloat16* __restrict__ hi,
                           __nv_bfloat16* __restrict__ lo, int n4) {
    int i = blockIdx.x * 256 + threadIdx.x;
    if (i >= n4) return;
    float4 v = ((const float4*)src)[i];
    __nv_bfloat16 hx = __float2bfloat16_rn(v.x);
    __nv_bfloat16 hy = __float2bfloat16_rn(v.y);
    __nv_bfloat16 hz = __float2bfloat16_rn(v.z);
    __nv_bfloat16 hw = __float2bfloat16_rn(v.w);
    __nv_bfloat16 lx = __float2bfloat16_rn(v.x - __bfloat162float(hx));
    __nv_bfloat16 ly = __float2bfloat16_rn(v.y - __bfloat162float(hy));
    __nv_bfloat16 lz = __float2bfloat16_rn(v.z - __bfloat162float(hz));
    __nv_bfloat16 lw = __float2bfloat16_rn(v.w - __bfloat162float(hw));
    uint2 ho, loo;
    ho.x  = (uint32_t)__bfloat16_as_ushort(hx) | ((uint32_t)__bfloat16_as_ushort(hy) << 16);
    ho.y  = (uint32_t)__bfloat16_as_ushort(hz) | ((uint32_t)__bfloat16_as_ushort(hw) << 16);
    loo.x = (uint32_t)__bfloat16_as_ushort(lx) | ((uint32_t)__bfloat16_as_ushort(ly) << 16);
    loo.y = (uint32_t)__bfloat16_as_ushort(lz) | ((uint32_t)__bfloat16_as_ushort(lw) << 16);
    ((uint2*)hi)[i] = ho;
    ((uint2*)lo)[i] = loo;
}

// ---------------- HMMA bf16x3 GEMM: C[M,N] = A[M,512] @ W[N,512]^T + bias ----------------
// CTA 128x128, K chunks of 64, double-buffered cp.async, 8 warps of 64x32 tiles.
#define GEMM_SMEM (2 * 4 * 16384)

__device__ __forceinline__ void cpasync16(uint32_t dst, const void* src) {
    asm volatile("cp.async.cg.shared.global [%0], [%1], 16;" :: "r"(dst), "l"(src));
}

__device__ __forceinline__ void ldmx4(uint32_t* r, uint32_t addr) {
    asm volatile("ldmatrix.sync.aligned.m8n8.x4.shared.b16 {%0,%1,%2,%3}, [%4];"
                 : "=r"(r[0]), "=r"(r[1]), "=r"(r[2]), "=r"(r[3]) : "r"(addr));
}

__device__ __forceinline__ void mma16816(float* d, const uint32_t* a, const uint32_t* b) {
    asm volatile("mma.sync.aligned.m16n8k16.row.col.f32.bf16.bf16.f32 "
                 "{%0,%1,%2,%3}, {%4,%5,%6,%7}, {%8,%9}, {%0,%1,%2,%3};"
                 : "+f"(d[0]), "+f"(d[1]), "+f"(d[2]), "+f"(d[3])
                 : "r"(a[0]), "r"(a[1]), "r"(a[2]), "r"(a[3]), "r"(b[0]), "r"(b[1]));
}

__global__ __launch_bounds__(256, 1)
void gemm_hmma(const __nv_bfloat16* __restrict__ Ah, const __nv_bfloat16* __restrict__ Al,
               const __nv_bfloat16* __restrict__ Bh, const __nv_bfloat16* __restrict__ Bl,
               const float* __restrict__ bias, float* __restrict__ C, int N, int relu) {
    extern __shared__ __align__(1024) char sm[];
    uint32_t sb = smem_u32(sm);
    int t = threadIdx.x;
    int lane = t & 31, warp = t >> 5;
    int m0 = blockIdx.y * 128, n0 = blockIdx.x * 128;
    int wm = warp & 1, wn = warp >> 1;   // warp tile: (wm*64, wn*32)

    const __nv_bfloat16* srcs[4] = { Ah, Al, Bh, Bl };
    int rowbase[4] = { m0, m0, n0, n0 };

    float acc[4][4][4];
    #pragma unroll
    for (int a = 0; a < 4; a++)
        #pragma unroll
        for (int b = 0; b < 4; b++)
            #pragma unroll
            for (int c = 0; c < 4; c++) acc[a][b][c] = 0.f;

    // async loader for one K-chunk (64 k) of all 4 tiles into stage ST
    auto load_chunk = [&](int CH, int ST) {
        uint32_t stb = sb + ST * 65536;
        #pragma unroll
        for (int tile = 0; tile < 4; tile++) {
            #pragma unroll
            for (int it = 0; it < 4; it++) {
                int idx = t + it * 256;
                int row = idx >> 3, c16 = idx & 7;
                uint32_t doff = (uint32_t)(row * 128 + ((c16 * 16) ^ ((row & 7) << 4)));
                const __nv_bfloat16* s = srcs[tile] +
                    (size_t)(rowbase[tile] + row) * 512 + CH * 64 + c16 * 8;
                cpasync16(stb + tile * 16384 + doff, s);
            }
        }
        asm volatile("cp.async.commit_group;" ::: "memory");
    };

    load_chunk(0, 0);
    load_chunk(1, 1);

    // lane-invariant address components
    uint32_t axor = (lane & 7) << 4;
    uint32_t arow = (uint32_t)(wm * 64 + (lane & 15)) * 128;
    uint32_t asel = 16u * ((lane >> 4) & 1);
    uint32_t brow = (uint32_t)(wn * 32 + (lane & 7) + 8 * ((lane >> 4) & 1)) * 128;
    uint32_t bsel = 16u * ((lane >> 3) & 1);

    #pragma unroll
    for (int ch = 0; ch < 8; ch++) {
        if (ch < 7) asm volatile("cp.async.wait_group 1;" ::: "memory");
        else        asm volatile("cp.async.wait_group 0;" ::: "memory");
        __syncthreads();
        uint32_t stb = sb + (ch & 1) * 65536;
        uint32_t tAh = stb, tAl = stb + 16384, tBh = stb + 32768, tBl = stb + 49152;
        #pragma unroll
        for (int ks = 0; ks < 4; ks++) {
            uint32_t kb = ks * 32;  // k16 block byte offset
            uint32_t ah[4][4], al[4][4], bh[2][4], bl[2][4];
            #pragma unroll
            for (int mf = 0; mf < 4; mf++) {
                uint32_t off = arow + mf * 2048 + ((kb + asel) ^ axor);
                ldmx4(ah[mf], tAh + off);
                ldmx4(al[mf], tAl + off);
            }
            #pragma unroll
            for (int nf16 = 0; nf16 < 2; nf16++) {
                uint32_t off = brow + nf16 * 2048 + ((kb + bsel) ^ axor);
                ldmx4(bh[nf16], tBh + off);
                ldmx4(bl[nf16], tBl + off);
            }
            #pragma unroll
            for (int mf = 0; mf < 4; mf++)
                #pragma unroll
                for (int nf = 0; nf < 4; nf++) {
                    const uint32_t* Bh2 = &bh[nf >> 1][(nf & 1) * 2];
                    const uint32_t* Bl2 = &bl[nf >> 1][(nf & 1) * 2];
                    mma16816(acc[mf][nf], ah[mf], Bh2);
                    mma16816(acc[mf][nf], ah[mf], Bl2);
                    mma16816(acc[mf][nf], al[mf], Bh2);
                }
        }
        __syncthreads();
        if (ch + 2 < 8) load_chunk(ch + 2, ch & 1);
    }

    // epilogue
    int g = lane >> 2, tg = lane & 3;
    #pragma unroll
    for (int mf = 0; mf < 4; mf++) {
        int r0 = m0 + wm * 64 + mf * 16 + g;
        #pragma unroll
        for (int nf = 0; nf < 4; nf++) {
            int c0 = n0 + wn * 32 + nf * 8 + tg * 2;
            float b0 = bias[c0], b1 = bias[c0 + 1];
            float2 v0 = make_float2(acc[mf][nf][0] + b0, acc[mf][nf][1] + b1);
            float2 v1 = make_float2(acc[mf][nf][2] + b0, acc[mf][nf][3] + b1);
            if (relu) {
                v0.x = fmaxf(v0.x, 0.f); v0.y = fmaxf(v0.y, 0.f);
                v1.x = fmaxf(v1.x, 0.f); v1.y = fmaxf(v1.y, 0.f);
            }
            *(float2*)(C + (size_t)r0 * N + c0) = v0;
            *(float2*)(C + (size_t)(r0 + 8) * N + c0) = v1;
        }
    }
}

// ---------------- fused masked-causal attention (online softmax) ----------------
__global__ __launch_bounds__(128, 1)
void attn_kernel(const float* __restrict__ qp, const float* __restrict__ kv,
                 float* __restrict__ out) {
    __shared__ float Ks[32][64];
    __shared__ float Vs[32][64];
    __shared__ float Ms[L];
    int bh = blockIdx.x;
    int b = bh >> 3, h = bh & 7;
    int t = threadIdx.x;
    int i = blockIdx.y * 128 + t;

    const float* qb = qp + ((size_t)(b * L + i)) * E + h * HD;
    float q[64];
    #pragma unroll
    for (int d4 = 0; d4 < 16; d4++) {
        float4 v = *(const float4*)(qb + d4 * 4);
        q[d4 * 4] = v.x; q[d4 * 4 + 1] = v.y; q[d4 * 4 + 2] = v.z; q[d4 * 4 + 3] = v.w;
    }
    #pragma unroll
    for (int c = 0; c < 8; c++) Ms[t + 128 * c] = g_m[t + 128 * c];

    float acc[64];
    #pragma unroll
    for (int d = 0; d < 64; d++) acc[d] = 0.f;
    float mx = -1e30f, sum = 0.f;

    int ntiles = (blockIdx.y + 1) * 4;
    for (int tile = 0; tile < ntiles; tile++) {
        int j0 = tile * 32;
        __syncthreads();
        #pragma unroll
        for (int c = 0; c < 4; c++) {
            int idx = t + 128 * c;
            int row = idx >> 4;
            int col = (idx & 15) * 4;
            size_t off = ((size_t)(b * L + j0 + row)) * (2 * E) + h * HD + col;
            *(float4*)&Ks[row][col] = *(const float4*)(kv + off);
            *(float4*)&Vs[row][col] = *(const float4*)(kv + off + E);
        }
        __syncthreads();
        for (int jj = 0; jj < 32; jj++) {
            int j = j0 + jj;
            if (j > i) break;
            if (Ms[i - j] == 0.f) continue;
            float s = 0.f;
            #pragma unroll
            for (int d4 = 0; d4 < 16; d4++) {
                float4 kvv = *(const float4*)&Ks[jj][d4 * 4];
                s += q[d4 * 4] * kvv.x + q[d4 * 4 + 1] * kvv.y
                   + q[d4 * 4 + 2] * kvv.z + q[d4 * 4 + 3] * kvv.w;
            }
            s *= 0.125f;
            if (s > mx) {
                float f = __expf(mx - s);
                sum *= f;
                #pragma unroll
                for (int d = 0; d < 64; d++) acc[d] *= f;
                mx = s;
            }
            float p = __expf(s - mx);
            sum += p;
            #pragma unroll
            for (int d4 = 0; d4 < 16; d4++) {
                float4 vv = *(const float4*)&Vs[jj][d4 * 4];
                acc[d4 * 4]     += p * vv.x;
                acc[d4 * 4 + 1] += p * vv.y;
                acc[d4 * 4 + 2] += p * vv.z;
                acc[d4 * 4 + 3] += p * vv.w;
            }
        }
    }
    float inv = 1.f / sum;
    float* ob = out + ((size_t)(b * L + i)) * E + h * HD;
    #pragma unroll
    for (int d4 = 0; d4 < 16; d4++) {
        *(float4*)(ob + d4 * 4) = make_float4(acc[d4 * 4] * inv, acc[d4 * 4 + 1] * inv,
                                              acc[d4 * 4 + 2] * inv, acc[d4 * 4 + 3] * inv);
    }
}

// ---------------- out = LayerNorm(a + b) * s + bb ----------------
__global__ void addln_kernel(const float* __restrict__ a, const float* __restrict__ b,
                             const float* __restrict__ s, const float* __restrict__ bb,
                             float* __restrict__ out) {
    int tkn = blockIdx.x;
    int t = threadIdx.x;
    __shared__ float sh[4];
    float4 av = ((const float4*)a)[tkn * 128 + t];
    float4 bv = ((const float4*)b)[tkn * 128 + t];
    float4 v = make_float4(av.x + bv.x, av.y + bv.y, av.z + bv.z, av.w + bv.w);
    float total = blockSum128(v.x + v.y + v.z + v.w, sh);
    float mean = total * (1.f / 512.f);
    float dx = v.x - mean, dy = v.y - mean, dz = v.z - mean, dw = v.w - mean;
    float vtot = blockSum128(dx * dx + dy * dy + dz * dz + dw * dw, sh);
    float inv = rsqrtf(vtot * (1.f / 512.f) + 1e-5f);
    float4 sv = ((const float4*)s)[t];
    float4 bv2 = ((const float4*)bb)[t];
    ((float4*)out)[tkn * 128 + t] = make_float4(dx * inv * sv.x + bv2.x, dy * inv * sv.y + bv2.y,
                                                dz * inv * sv.z + bv2.z, dw * inv * sv.w + bv2.w);
}

// ---------------- p = sigmoid(x . w + b) ----------------
__global__ void pred_kernel(const float* __restrict__ w, const float* __restrict__ pb,
                            float* __restrict__ out) {
    int tkn = blockIdx.x;
    int t = threadIdx.x;
    __shared__ float sh[4];
    float4 xv = ((const float4*)g_x)[tkn * 128 + t];
    float4 wv = ((const float4*)w)[t];
    float local = xv.x * wv.x + xv.y * wv.y + xv.z * wv.z + xv.w * wv.w;
    float z = blockSum128(local, sh) + pb[0];
    if (t == 0) out[tkn] = 1.f / (1.f + __expf(-z));
}

// ---------------- launch ----------------
extern "C" void kernel_launch(void* const* d_in, const int* in_sizes, int n_in,
                              void* d_out, int out_size) {
    const int*   q      = (const int*)d_in[0];
    const int*   r      = (const int*)d_in[1];
    const int*   qry    = (const int*)d_in[2];
    const float* alphas = (const float*)d_in[3];
    const float* gumbel = (const float*)d_in[4];
    const float* inter  = (const float*)d_in[5];
    const float* ex     = (const float*)d_in[6];
    const float* pos    = (const float*)d_in[7];
    const float* Wqkv   = (const float*)d_in[8];
    const float* bqkv   = (const float*)d_in[9];
    const float* Wo     = (const float*)d_in[10];
    const float* bo     = (const float*)d_in[11];
    const float* ln1_s  = (const float*)d_in[12];
    const float* ln1_b  = (const float*)d_in[13];
    const float* W1     = (const float*)d_in[14];
    const float* b1     = (const float*)d_in[15];
    const float* W2     = (const float*)d_in[16];
    const float* b2     = (const float*)d_in[17];
    const float* ln2_s  = (const float*)d_in[18];
    const float* ln2_b  = (const float*)d_in[19];
    const float* predw  = (const float*)d_in[20];
    const float* predb  = (const float*)d_in[21];
    float* out = (float*)d_out;

    cudaFuncSetAttribute(gemm_hmma, cudaFuncAttributeMaxDynamicSharedMemorySize, GEMM_SMEM);

    float *px, *pqsh, *pqp, *pkv, *patt, *pproj, *ph, *pff1;
    cudaGetSymbolAddress((void**)&px, g_x);
    cudaGetSymbolAddress((void**)&pqsh, g_qsh);
    cudaGetSymbolAddress((void**)&pqp, g_qp);
    cudaGetSymbolAddress((void**)&pkv, g_kv);
    cudaGetSymbolAddress((void**)&patt, g_att);
    cudaGetSymbolAddress((void**)&pproj, g_proj);
    cudaGetSymbolAddress((void**)&ph, g_h);
    cudaGetSymbolAddress((void**)&pff1, g_ff1);
    __nv_bfloat16 *pqh, *pql, *pah, *pal, *pwh, *pwl;
    cudaGetSymbolAddress((void**)&pqh, g_qh);
    cudaGetSymbolAddress((void**)&pql, g_ql);
    cudaGetSymbolAddress((void**)&pah, g_ah);
    cudaGetSymbolAddress((void**)&pal, g_al);
    cudaGetSymbolAddress((void**)&pwh, g_wh);
    cudaGetSymbolAddress((void**)&pwl, g_wl);

    embed_kernel<<<BL, 128>>>(q, r, qry, inter, ex, pos);
    mask_kernel<<<1, 1024>>>(alphas, gumbel, out + BL);

    const int ACT4 = BL * E / 4;
    conv_split<<<(6 * EE / 4 + 255) / 256, 256>>>(Wqkv, pwh, pwl, 6 * EE / 4);
    conv_split<<<(2 * EE / 4 + 255) / 256, 256>>>(Wo, pwh + 6 * EE, pwl + 6 * EE, 2 * EE / 4);
    conv_split<<<(2 * EE / 4 + 255) / 256, 256>>>(W1, pwh + 8 * EE, pwl + 8 * EE, 2 * EE / 4);
    conv_split<<<(2 * EE / 4 + 255) / 256, 256>>>(W2, pwh + 10 * EE, pwl + 10 * EE, 2 * EE / 4);
    conv_split<<<(ACT4 + 255) / 256, 256>>>(pqsh, pqh, pql, ACT4);

    dim3 g512(4, 64);
    dim3 g1024(8, 64);
    dim3 agrid(BATCH * NH, L / 128);
    const int CV = (ACT4 + 255) / 256;

    for (int l = 0; l < 2; l++) {
        const float* bl = bqkv + (size_t)l * 3 * E;
        size_t wq = (size_t)l * 3 * EE;
        gemm_hmma<<<g512, 256, GEMM_SMEM>>>(pqh, pql, pwh + wq, pwl + wq, bl, pqp, 512, 0);
        conv_split<<<CV, 256>>>(px, pah, pal, ACT4);
        gemm_hmma<<<g1024, 256, GEMM_SMEM>>>(pah, pal, pwh + wq + EE, pwl + wq + EE, bl + E, pkv, 1024, 0);
        attn_kernel<<<agrid, 128>>>(pqp, pkv, patt);
        conv_split<<<CV, 256>>>(patt, pah, pal, ACT4);
        gemm_hmma<<<g512, 256, GEMM_SMEM>>>(pah, pal, pwh + (6 + l) * EE, pwl + (6 + l) * EE,
                                            bo + l * E, pproj, 512, 0);
        addln_kernel<<<BL, 128>>>(pqsh, pproj, ln1_s + l * E, ln1_b + l * E, ph);
        conv_split<<<CV, 256>>>(ph, pah, pal, ACT4);
        gemm_hmma<<<g512, 256, GEMM_SMEM>>>(pah, pal, pwh + (8 + l) * EE, pwl + (8 + l) * EE,
                                            b1 + l * E, pff1, 512, 1);
        conv_split<<<CV, 256>>>(pff1, pah, pal, ACT4);
        gemm_hmma<<<g512, 256, GEMM_SMEM>>>(pah, pal, pwh + (10 + l) * EE, pwl + (10 + l) * EE,
                                            b2 + l * E, pproj, 512, 0);
        addln_kernel<<<BL, 128>>>(ph, pproj, ln2_s + l * E, ln2_b + l * E, px);
    }

    pred_kernel<<<BL, 128>>>(predw, predb, out);
}

// round 6
// speedup vs baseline: 3.1864x; 2.0315x over previous
#include <cuda_runtime.h>
#include <cuda_bf16.h>
#include <math.h>
#include <stdint.h>

#define L 1024
#define BATCH 8
#define E 512
#define NH 8
#define HD 64
#define BL (BATCH * L)
#define NUMC 10000
#define EE (E * E)

// ---------------- scratch (static device globals; no allocation) ----------------
__device__ float g_x[BL * E];
__device__ float g_qsh[BL * E];
__device__ float g_proj[BL * E];
__device__ float g_h[BL * E];
__device__ float g_m[L];

// bf16 hi/lo split buffers
__device__ __nv_bfloat16 g_qshh[BL * E], g_qshl[BL * E];
__device__ __nv_bfloat16 g_xh[BL * E],   g_xl[BL * E];
__device__ __nv_bfloat16 g_hh[BL * E],   g_hl[BL * E];
__device__ __nv_bfloat16 g_qph[BL * E],  g_qpl[BL * E];
__device__ __nv_bfloat16 g_kvh[BL * 2 * E], g_kvl[BL * 2 * E];
__device__ __nv_bfloat16 g_atth[BL * E], g_attl[BL * E];
__device__ __nv_bfloat16 g_f1h[BL * E],  g_f1l[BL * E];
__device__ __nv_bfloat16 g_wh[12 * EE],  g_wl[12 * EE];

// ---------------- helpers ----------------
__device__ __forceinline__ float blockSum128(float v, float* sh) {
    int lane = threadIdx.x & 31, w = threadIdx.x >> 5;
    #pragma unroll
    for (int o = 16; o > 0; o >>= 1) v += __shfl_xor_sync(0xffffffffu, v, o);
    if (lane == 0) sh[w] = v;
    __syncthreads();
    float r = sh[0] + sh[1] + sh[2] + sh[3];
    __syncthreads();
    return r;
}

__device__ __forceinline__ uint32_t smem_u32(const void* p) {
    uint32_t a;
    asm("{ .reg .u64 t; cvta.to.shared.u64 t, %1; cvt.u32.u64 %0, t; }" : "=r"(a) : "l"(p));
    return a;
}

// split pair of floats into packed bf16x2 hi and lo
__device__ __forceinline__ void split2(float a, float b, uint32_t& hi, uint32_t& lo) {
    __nv_bfloat16 ha = __float2bfloat16_rn(a), hb = __float2bfloat16_rn(b);
    float fa = __bfloat162float(ha), fb = __bfloat162float(hb);
    __nv_bfloat16 la = __float2bfloat16_rn(a - fa), lb = __float2bfloat16_rn(b - fb);
    hi = (uint32_t)__bfloat16_as_ushort(ha) | ((uint32_t)__bfloat16_as_ushort(hb) << 16);
    lo = (uint32_t)__bfloat16_as_ushort(la) | ((uint32_t)__bfloat16_as_ushort(lb) << 16);
}

__device__ __forceinline__ void split4_store(float4 v, __nv_bfloat16* hi, __nv_bfloat16* lo, size_t u2idx) {
    uint2 h, l;
    split2(v.x, v.y, h.x, l.x);
    split2(v.z, v.w, h.y, l.y);
    ((uint2*)hi)[u2idx] = h;
    ((uint2*)lo)[u2idx] = l;
}

// ---------------- embed (also emits x and qsh splits) ----------------
__global__ void embed_kernel(const int* __restrict__ q, const int* __restrict__ r,
                             const int* __restrict__ qry,
                             const float* __restrict__ inter,
                             const float* __restrict__ ex,
                             const float* __restrict__ pos) {
    int t = blockIdx.x;
    int l = t & (L - 1);
    int e4 = threadIdx.x;
    int rowx = q[t] + NUMC * r[t];
    float4 a = ((const float4*)inter)[rowx * (E / 4) + e4];
    float4 p = ((const float4*)pos)[l * (E / 4) + e4];
    float4 xv = make_float4(a.x + p.x, a.y + p.y, a.z + p.z, a.w + p.w);
    float4 qv = ((const float4*)ex)[qry[t] * (E / 4) + e4];
    size_t fi = (size_t)t * 128 + e4;
    ((float4*)g_x)[fi] = xv;
    ((float4*)g_qsh)[fi] = qv;
    split4_store(xv, g_xh, g_xl, fi);
    split4_store(qv, g_qshh, g_qshl, fi);
}

// ---------------- mask ----------------
__global__ void mask_kernel(const float* __restrict__ alphas,
                            const float* __restrict__ gumbel,
                            float* __restrict__ out_l1) {
    int i = threadIdx.x;
    float a0 = alphas[2 * i], a1 = alphas[2 * i + 1];
    float z0 = a0 + gumbel[2 * i], z1 = a1 + gumbel[2 * i + 1];
    g_m[i] = (z0 >= z1) ? 1.0f : 0.0f;
    float v = fabsf(a0) + fabsf(a1);
    __shared__ float sh[32];
    int lane = i & 31, w = i >> 5;
    #pragma unroll
    for (int o = 16; o > 0; o >>= 1) v += __shfl_xor_sync(0xffffffffu, v, o);
    if (lane == 0) sh[w] = v;
    __syncthreads();
    if (i < 32) {
        float x = sh[i];
        #pragma unroll
        for (int o = 16; o > 0; o >>= 1) x += __shfl_xor_sync(0xffffffffu, x, o);
        if (i == 0) out_l1[0] = x;
    }
}

// ---------------- fp32 -> bf16 hi/lo split (weights only) ----------------
__global__ void conv_split(const float* __restrict__ src,
                           __nv_bfloat16* __restrict__ hi,
                           __nv_bfloat16* __restrict__ lo, int n4) {
    int i = blockIdx.x * 256 + threadIdx.x;
    if (i >= n4) return;
    float4 v = ((const float4*)src)[i];
    split4_store(v, hi, lo, i);
}

// ---------------- MMA primitives ----------------
__device__ __forceinline__ void cpasync16(uint32_t dst, const void* src) {
    asm volatile("cp.async.cg.shared.global [%0], [%1], 16;" :: "r"(dst), "l"(src));
}
__device__ __forceinline__ void ldmx4(uint32_t* r, uint32_t addr) {
    asm volatile("ldmatrix.sync.aligned.m8n8.x4.shared.b16 {%0,%1,%2,%3}, [%4];"
                 : "=r"(r[0]), "=r"(r[1]), "=r"(r[2]), "=r"(r[3]) : "r"(addr));
}
__device__ __forceinline__ void ldmx4t(uint32_t* r, uint32_t addr) {
    asm volatile("ldmatrix.sync.aligned.m8n8.x4.trans.shared.b16 {%0,%1,%2,%3}, [%4];"
                 : "=r"(r[0]), "=r"(r[1]), "=r"(r[2]), "=r"(r[3]) : "r"(addr));
}
__device__ __forceinline__ void mma16816(float* d, const uint32_t* a, const uint32_t* b) {
    asm volatile("mma.sync.aligned.m16n8k16.row.col.f32.bf16.bf16.f32 "
                 "{%0,%1,%2,%3}, {%4,%5,%6,%7}, {%8,%9}, {%0,%1,%2,%3};"
                 : "+f"(d[0]), "+f"(d[1]), "+f"(d[2]), "+f"(d[3])
                 : "r"(a[0]), "r"(a[1]), "r"(a[2]), "r"(a[3]), "r"(b[0]), "r"(b[1]));
}

// ---------------- HMMA bf16x3 GEMM: C[M,N] = A[M,512] @ W[N,512]^T + bias ----------------
#define GEMM_SMEM (2 * 4 * 16384)
__global__ __launch_bounds__(256, 1)
void gemm_hmma(const __nv_bfloat16* __restrict__ Ah, const __nv_bfloat16* __restrict__ Al,
               const __nv_bfloat16* __restrict__ Bh, const __nv_bfloat16* __restrict__ Bl,
               const float* __restrict__ bias, float* __restrict__ C,
               __nv_bfloat16* __restrict__ Chi, __nv_bfloat16* __restrict__ Clo,
               int N, int relu, int writeC) {
    extern __shared__ __align__(1024) char sm[];
    uint32_t sb = smem_u32(sm);
    int t = threadIdx.x;
    int lane = t & 31, warp = t >> 5;
    int m0 = blockIdx.y * 128, n0 = blockIdx.x * 128;
    int wm = warp & 1, wn = warp >> 1;

    const __nv_bfloat16* srcs[4] = { Ah, Al, Bh, Bl };
    int rowbase[4] = { m0, m0, n0, n0 };

    float acc[4][4][4];
    #pragma unroll
    for (int a = 0; a < 4; a++)
        #pragma unroll
        for (int b = 0; b < 4; b++)
            #pragma unroll
            for (int c = 0; c < 4; c++) acc[a][b][c] = 0.f;

    auto load_chunk = [&](int CH, int ST) {
        uint32_t stb = sb + ST * 65536;
        #pragma unroll
        for (int tile = 0; tile < 4; tile++) {
            #pragma unroll
            for (int it = 0; it < 4; it++) {
                int idx = t + it * 256;
                int row = idx >> 3, c16 = idx & 7;
                uint32_t doff = (uint32_t)(row * 128 + ((c16 * 16) ^ ((row & 7) << 4)));
                const __nv_bfloat16* s = srcs[tile] +
                    (size_t)(rowbase[tile] + row) * 512 + CH * 64 + c16 * 8;
                cpasync16(stb + tile * 16384 + doff, s);
            }
        }
        asm volatile("cp.async.commit_group;" ::: "memory");
    };

    load_chunk(0, 0);
    load_chunk(1, 1);

    uint32_t axor = (lane & 7) << 4;
    uint32_t arow = (uint32_t)(wm * 64 + (lane & 15)) * 128;
    uint32_t asel = 16u * ((lane >> 4) & 1);
    uint32_t brow = (uint32_t)(wn * 32 + (lane & 7) + 8 * ((lane >> 4) & 1)) * 128;
    uint32_t bsel = 16u * ((lane >> 3) & 1);

    #pragma unroll
    for (int ch = 0; ch < 8; ch++) {
        if (ch < 7) asm volatile("cp.async.wait_group 1;" ::: "memory");
        else        asm volatile("cp.async.wait_group 0;" ::: "memory");
        __syncthreads();
        uint32_t stb = sb + (ch & 1) * 65536;
        uint32_t tAh = stb, tAl = stb + 16384, tBh = stb + 32768, tBl = stb + 49152;
        #pragma unroll
        for (int ks = 0; ks < 4; ks++) {
            uint32_t kb = ks * 32;
            uint32_t ah[4][4], al[4][4], bh[2][4], bl[2][4];
            #pragma unroll
            for (int mf = 0; mf < 4; mf++) {
                uint32_t off = arow + mf * 2048 + ((kb + asel) ^ axor);
                ldmx4(ah[mf], tAh + off);
                ldmx4(al[mf], tAl + off);
            }
            #pragma unroll
            for (int nf16 = 0; nf16 < 2; nf16++) {
                uint32_t off = brow + nf16 * 2048 + ((kb + bsel) ^ axor);
                ldmx4(bh[nf16], tBh + off);
                ldmx4(bl[nf16], tBl + off);
            }
            #pragma unroll
            for (int mf = 0; mf < 4; mf++)
                #pragma unroll
                for (int nf = 0; nf < 4; nf++) {
                    const uint32_t* Bh2 = &bh[nf >> 1][(nf & 1) * 2];
                    const uint32_t* Bl2 = &bl[nf >> 1][(nf & 1) * 2];
                    mma16816(acc[mf][nf], ah[mf], Bh2);
                    mma16816(acc[mf][nf], ah[mf], Bl2);
                    mma16816(acc[mf][nf], al[mf], Bh2);
                }
        }
        __syncthreads();
        if (ch + 2 < 8) load_chunk(ch + 2, ch & 1);
    }

    int g = lane >> 2, tg = lane & 3;
    #pragma unroll
    for (int mf = 0; mf < 4; mf++) {
        int r0 = m0 + wm * 64 + mf * 16 + g;
        #pragma unroll
        for (int nf = 0; nf < 4; nf++) {
            int c0 = n0 + wn * 32 + nf * 8 + tg * 2;
            float b0 = bias[c0], b1 = bias[c0 + 1];
            float2 v0 = make_float2(acc[mf][nf][0] + b0, acc[mf][nf][1] + b1);
            float2 v1 = make_float2(acc[mf][nf][2] + b0, acc[mf][nf][3] + b1);
            if (relu) {
                v0.x = fmaxf(v0.x, 0.f); v0.y = fmaxf(v0.y, 0.f);
                v1.x = fmaxf(v1.x, 0.f); v1.y = fmaxf(v1.y, 0.f);
            }
            if (writeC) {
                *(float2*)(C + (size_t)r0 * N + c0) = v0;
                *(float2*)(C + (size_t)(r0 + 8) * N + c0) = v1;
            }
            if (Chi) {
                uint32_t h0, l0, h1, l1;
                split2(v0.x, v0.y, h0, l0);
                split2(v1.x, v1.y, h1, l1);
                ((uint32_t*)Chi)[((size_t)r0 * N + c0) >> 1] = h0;
                ((uint32_t*)Clo)[((size_t)r0 * N + c0) >> 1] = l0;
                ((uint32_t*)Chi)[((size_t)(r0 + 8) * N + c0) >> 1] = h1;
                ((uint32_t*)Clo)[((size_t)(r0 + 8) * N + c0) >> 1] = l1;
            }
        }
    }
}

// ---------------- HMMA flash attention, bf16x3, masked causal ----------------
// grid (B*NH, 8), block 128 (4 warps x 32 q-rows). K-tiles of 32 keys.
#define ATT_SMEM 53248
__global__ __launch_bounds__(128, 1)
void attn_hmma(const __nv_bfloat16* __restrict__ Qh, const __nv_bfloat16* __restrict__ Ql,
               const __nv_bfloat16* __restrict__ KVh, const __nv_bfloat16* __restrict__ KVl,
               __nv_bfloat16* __restrict__ Oh, __nv_bfloat16* __restrict__ Ol) {
    extern __shared__ __align__(128) char sm[];
    const uint32_t oQh = 0, oQl = 16384, oKh = 32768, oKl = 36864, oVh = 40960, oVl = 45056;
    float* biasS = (float*)(sm + 49152);
    uint32_t sb = smem_u32(sm);
    int t = threadIdx.x, lane = t & 31, warp = t >> 5;
    int b = blockIdx.x >> 3, h = blockIdx.x & 7;
    int qb = blockIdx.y, qbase = qb * 128;

    for (int k = t; k < 1024; k += 128) biasS[k] = (g_m[k] != 0.f) ? 0.f : -1e30f;

    // stage Q hi/lo (128 rows x 64 halves, swizzled)
    #pragma unroll
    for (int it = 0; it < 8; it++) {
        int idx = t + it * 128;
        int row = idx >> 3, c = idx & 7;
        size_t goff = (size_t)(b * L + qbase + row) * 512 + h * 64 + c * 8;
        uint32_t doff = (uint32_t)(row * 128 + ((c ^ (row & 7)) << 4));
        *(uint4*)(sm + oQh + doff) = *(const uint4*)(Qh + goff);
        *(uint4*)(sm + oQl + doff) = *(const uint4*)(Ql + goff);
    }
    __syncthreads();

    // Q hi A-fragments, persistent
    uint32_t qfh[2][4][4];
    #pragma unroll
    for (int mf = 0; mf < 2; mf++)
        #pragma unroll
        for (int kk = 0; kk < 4; kk++) {
            int r = warp * 32 + mf * 16 + (lane & 15);
            int hb = kk * 2 + ((lane >> 4) & 1);
            ldmx4(qfh[mf][kk], sb + oQh + r * 128 + ((hb ^ (r & 7)) << 4));
        }

    float Ow[2][8][4];
    #pragma unroll
    for (int a = 0; a < 2; a++)
        #pragma unroll
        for (int bb = 0; bb < 8; bb++)
            #pragma unroll
            for (int c = 0; c < 4; c++) Ow[a][bb][c] = 0.f;
    float mx[2][2] = {{-1e4f, -1e4f}, {-1e4f, -1e4f}};
    float sums[2][2] = {{0.f, 0.f}, {0.f, 0.f}};
    int g = lane >> 2, tq = lane & 3;

    int ntiles = (qb + 1) * 4;
    for (int tile = 0; tile < ntiles; tile++) {
        int j0 = tile * 32;
        __syncthreads();
        #pragma unroll
        for (int it = 0; it < 2; it++) {
            int idx = t + it * 128;
            int row = idx >> 3, c = idx & 7;
            size_t koff = (size_t)(b * L + j0 + row) * 1024 + h * 64 + c * 8;
            uint32_t doff = (uint32_t)(row * 128 + ((c ^ (row & 7)) << 4));
            *(uint4*)(sm + oKh + doff) = *(const uint4*)(KVh + koff);
            *(uint4*)(sm + oKl + doff) = *(const uint4*)(KVl + koff);
            *(uint4*)(sm + oVh + doff) = *(const uint4*)(KVh + koff + 512);
            *(uint4*)(sm + oVl + doff) = *(const uint4*)(KVl + koff + 512);
        }
        __syncthreads();

        // S = Q K^T (bf16x3)
        float S[2][4][4];
        #pragma unroll
        for (int a = 0; a < 2; a++)
            #pragma unroll
            for (int bb = 0; bb < 4; bb++)
                #pragma unroll
                for (int c = 0; c < 4; c++) S[a][bb][c] = 0.f;

        #pragma unroll
        for (int kk = 0; kk < 4; kk++) {
            uint32_t qfl[2][4];
            #pragma unroll
            for (int mf = 0; mf < 2; mf++) {
                int r = warp * 32 + mf * 16 + (lane & 15);
                int hb = kk * 2 + ((lane >> 4) & 1);
                ldmx4(qfl[mf], sb + oQl + r * 128 + ((hb ^ (r & 7)) << 4));
            }
            #pragma unroll
            for (int pair = 0; pair < 2; pair++) {
                int kr = (pair * 2 + ((lane >> 4) & 1)) * 8 + (lane & 7);
                int hb = kk * 2 + ((lane >> 3) & 1);
                uint32_t off = (uint32_t)(kr * 128 + ((hb ^ (kr & 7)) << 4));
                uint32_t kh4[4], kl4[4];
                ldmx4(kh4, sb + oKh + off);
                ldmx4(kl4, sb + oKl + off);
                #pragma unroll
                for (int sub = 0; sub < 2; sub++) {
                    int ng = pair * 2 + sub;
                    #pragma unroll
                    for (int mf = 0; mf < 2; mf++) {
                        mma16816(S[mf][ng], qfh[mf][kk], kh4 + sub * 2);
                        mma16816(S[mf][ng], qfh[mf][kk], kl4 + sub * 2);
                        mma16816(S[mf][ng], qfl[mf],     kh4 + sub * 2);
                    }
                }
            }
        }

        // masked online softmax + P fragment build
        uint32_t Ph[2][2][4], Pl[2][2][4];
        #pragma unroll
        for (int mf = 0; mf < 2; mf++) {
            int i0 = qbase + warp * 32 + mf * 16 + g;
            int i1 = i0 + 8;
            float r0 = -1e30f, r1 = -1e30f;
            #pragma unroll
            for (int ng = 0; ng < 4; ng++)
                #pragma unroll
                for (int e = 0; e < 2; e++) {
                    int j = j0 + ng * 8 + tq * 2 + e;
                    float s0 = (j <= i0) ? S[mf][ng][e] * 0.125f + biasS[i0 - j] : -1e30f;
                    float s1 = (j <= i1) ? S[mf][ng][2 + e] * 0.125f + biasS[i1 - j] : -1e30f;
                    S[mf][ng][e] = s0; S[mf][ng][2 + e] = s1;
                    r0 = fmaxf(r0, s0); r1 = fmaxf(r1, s1);
                }
            r0 = fmaxf(r0, __shfl_xor_sync(0xffffffffu, r0, 1));
            r0 = fmaxf(r0, __shfl_xor_sync(0xffffffffu, r0, 2));
            r1 = fmaxf(r1, __shfl_xor_sync(0xffffffffu, r1, 1));
            r1 = fmaxf(r1, __shfl_xor_sync(0xffffffffu, r1, 2));
            float mN0 = fmaxf(mx[mf][0], r0), mN1 = fmaxf(mx[mf][1], r1);
            float f0 = __expf(mx[mf][0] - mN0), f1 = __expf(mx[mf][1] - mN1);
            mx[mf][0] = mN0; mx[mf][1] = mN1;
            float ps0 = 0.f, ps1 = 0.f;
            #pragma unroll
            for (int ng = 0; ng < 4; ng++)
                #pragma unroll
                for (int e = 0; e < 2; e++) {
                    float p0 = __expf(S[mf][ng][e] - mN0);
                    float p1 = __expf(S[mf][ng][2 + e] - mN1);
                    S[mf][ng][e] = p0; S[mf][ng][2 + e] = p1;
                    ps0 += p0; ps1 += p1;
                }
            ps0 += __shfl_xor_sync(0xffffffffu, ps0, 1);
            ps0 += __shfl_xor_sync(0xffffffffu, ps0, 2);
            ps1 += __shfl_xor_sync(0xffffffffu, ps1, 1);
            ps1 += __shfl_xor_sync(0xffffffffu, ps1, 2);
            sums[mf][0] = sums[mf][0] * f0 + ps0;
            sums[mf][1] = sums[mf][1] * f1 + ps1;
            #pragma unroll
            for (int nf = 0; nf < 8; nf++) {
                Ow[mf][nf][0] *= f0; Ow[mf][nf][1] *= f0;
                Ow[mf][nf][2] *= f1; Ow[mf][nf][3] *= f1;
            }
            #pragma unroll
            for (int kb = 0; kb < 2; kb++) {
                split2(S[mf][2 * kb][0],     S[mf][2 * kb][1],     Ph[mf][kb][0], Pl[mf][kb][0]);
                split2(S[mf][2 * kb][2],     S[mf][2 * kb][3],     Ph[mf][kb][1], Pl[mf][kb][1]);
                split2(S[mf][2 * kb + 1][0], S[mf][2 * kb + 1][1], Ph[mf][kb][2], Pl[mf][kb][2]);
                split2(S[mf][2 * kb + 1][2], S[mf][2 * kb + 1][3], Ph[mf][kb][3], Pl[mf][kb][3]);
            }
        }

        // O += P V (bf16x3)
        #pragma unroll
        for (int kb = 0; kb < 2; kb++)
            #pragma unroll
            for (int pair = 0; pair < 4; pair++) {
                int kr = kb * 16 + ((lane >> 3) & 1) * 8 + (lane & 7);
                int hb = pair * 2 + ((lane >> 4) & 1);
                uint32_t off = (uint32_t)(kr * 128 + ((hb ^ (kr & 7)) << 4));
                uint32_t vh4[4], vl4[4];
                ldmx4t(vh4, sb + oVh + off);
                ldmx4t(vl4, sb + oVl + off);
                #pragma unroll
                for (int sub = 0; sub < 2; sub++) {
                    int nf = pair * 2 + sub;
                    #pragma unroll
                    for (int mf = 0; mf < 2; mf++) {
                        mma16816(Ow[mf][nf], Ph[mf][kb], vh4 + sub * 2);
                        mma16816(Ow[mf][nf], Ph[mf][kb], vl4 + sub * 2);
                        mma16816(Ow[mf][nf], Pl[mf][kb], vh4 + sub * 2);
                    }
                }
            }
    }

    // epilogue: normalize, split, store
    #pragma unroll
    for (int mf = 0; mf < 2; mf++) {
        float inv0 = 1.f / sums[mf][0], inv1 = 1.f / sums[mf][1];
        int i0 = qbase + warp * 32 + mf * 16 + g;
        int i1 = i0 + 8;
        #pragma unroll
        for (int nf = 0; nf < 8; nf++) {
            int cc = h * 64 + nf * 8 + tq * 2;
            uint32_t h0, l0, h1, l1;
            split2(Ow[mf][nf][0] * inv0, Ow[mf][nf][1] * inv0, h0, l0);
            split2(Ow[mf][nf][2] * inv1, Ow[mf][nf][3] * inv1, h1, l1);
            ((uint32_t*)Oh)[((size_t)(b * L + i0) * 512 + cc) >> 1] = h0;
            ((uint32_t*)Ol)[((size_t)(b * L + i0) * 512 + cc) >> 1] = l0;
            ((uint32_t*)Oh)[((size_t)(b * L + i1) * 512 + cc) >> 1] = h1;
            ((uint32_t*)Ol)[((size_t)(b * L + i1) * 512 + cc) >> 1] = l1;
        }
    }
}

// ---------------- out = LayerNorm(a + b) * s + bb  (+ bf16 split) ----------------
__global__ void addln_kernel(const float* __restrict__ a, const float* __restrict__ b,
                             const float* __restrict__ s, const float* __restrict__ bb,
                             float* __restrict__ out,
                             __nv_bfloat16* __restrict__ outh, __nv_bfloat16* __restrict__ outl) {
    int tkn = blockIdx.x;
    int t = threadIdx.x;
    __shared__ float sh[4];
    float4 av = ((const float4*)a)[tkn * 128 + t];
    float4 bv = ((const float4*)b)[tkn * 128 + t];
    float4 v = make_float4(av.x + bv.x, av.y + bv.y, av.z + bv.z, av.w + bv.w);
    float total = blockSum128(v.x + v.y + v.z + v.w, sh);
    float mean = total * (1.f / 512.f);
    float dx = v.x - mean, dy = v.y - mean, dz = v.z - mean, dw = v.w - mean;
    float vtot = blockSum128(dx * dx + dy * dy + dz * dz + dw * dw, sh);
    float inv = rsqrtf(vtot * (1.f / 512.f) + 1e-5f);
    float4 sv = ((const float4*)s)[t];
    float4 bv2 = ((const float4*)bb)[t];
    float4 o = make_float4(dx * inv * sv.x + bv2.x, dy * inv * sv.y + bv2.y,
                           dz * inv * sv.z + bv2.z, dw * inv * sv.w + bv2.w);
    size_t fi = (size_t)tkn * 128 + t;
    ((float4*)out)[fi] = o;
    split4_store(o, outh, outl, fi);
}

// ---------------- p = sigmoid(x . w + b) ----------------
__global__ void pred_kernel(const float* __restrict__ w, const float* __restrict__ pb,
                            float* __restrict__ out) {
    int tkn = blockIdx.x;
    int t = threadIdx.x;
    __shared__ float sh[4];
    float4 xv = ((const float4*)g_x)[tkn * 128 + t];
    float4 wv = ((const float4*)w)[t];
    float local = xv.x * wv.x + xv.y * wv.y + xv.z * wv.z + xv.w * wv.w;
    float z = blockSum128(local, sh) + pb[0];
    if (t == 0) out[tkn] = 1.f / (1.f + __expf(-z));
}

// ---------------- launch ----------------
extern "C" void kernel_launch(void* const* d_in, const int* in_sizes, int n_in,
                              void* d_out, int out_size) {
    const int*   q      = (const int*)d_in[0];
    const int*   r      = (const int*)d_in[1];
    const int*   qry    = (const int*)d_in[2];
    const float* alphas = (const float*)d_in[3];
    const float* gumbel = (const float*)d_in[4];
    const float* inter  = (const float*)d_in[5];
    const float* ex     = (const float*)d_in[6];
    const float* pos    = (const float*)d_in[7];
    const float* Wqkv   = (const float*)d_in[8];
    const float* bqkv   = (const float*)d_in[9];
    const float* Wo     = (const float*)d_in[10];
    const float* bo     = (const float*)d_in[11];
    const float* ln1_s  = (const float*)d_in[12];
    const float* ln1_b  = (const float*)d_in[13];
    const float* W1     = (const float*)d_in[14];
    const float* b1     = (const float*)d_in[15];
    const float* W2     = (const float*)d_in[16];
    const float* b2     = (const float*)d_in[17];
    const float* ln2_s  = (const float*)d_in[18];
    const float* ln2_b  = (const float*)d_in[19];
    const float* predw  = (const float*)d_in[20];
    const float* predb  = (const float*)d_in[21];
    float* out = (float*)d_out;

    static int attr_done = 0;
    cudaFuncSetAttribute(gemm_hmma, cudaFuncAttributeMaxDynamicSharedMemorySize, GEMM_SMEM);
    cudaFuncSetAttribute(attn_hmma, cudaFuncAttributeMaxDynamicSharedMemorySize, ATT_SMEM);
    (void)attr_done;

    float *px, *pqsh, *pproj, *ph;
    cudaGetSymbolAddress((void**)&px, g_x);
    cudaGetSymbolAddress((void**)&pqsh, g_qsh);
    cudaGetSymbolAddress((void**)&pproj, g_proj);
    cudaGetSymbolAddress((void**)&ph, g_h);
    __nv_bfloat16 *pqshh, *pqshl, *pxh, *pxl, *phh, *phl, *pqph, *pqpl,
                  *pkvh, *pkvl, *path, *patl, *pf1h, *pf1l, *pwh, *pwl;
    cudaGetSymbolAddress((void**)&pqshh, g_qshh); cudaGetSymbolAddress((void**)&pqshl, g_qshl);
    cudaGetSymbolAddress((void**)&pxh, g_xh);     cudaGetSymbolAddress((void**)&pxl, g_xl);
    cudaGetSymbolAddress((void**)&phh, g_hh);     cudaGetSymbolAddress((void**)&phl, g_hl);
    cudaGetSymbolAddress((void**)&pqph, g_qph);   cudaGetSymbolAddress((void**)&pqpl, g_qpl);
    cudaGetSymbolAddress((void**)&pkvh, g_kvh);   cudaGetSymbolAddress((void**)&pkvl, g_kvl);
    cudaGetSymbolAddress((void**)&path, g_atth);  cudaGetSymbolAddress((void**)&patl, g_attl);
    cudaGetSymbolAddress((void**)&pf1h, g_f1h);   cudaGetSymbolAddress((void**)&pf1l, g_f1l);
    cudaGetSymbolAddress((void**)&pwh, g_wh);     cudaGetSymbolAddress((void**)&pwl, g_wl);

    embed_kernel<<<BL, 128>>>(q, r, qry, inter, ex, pos);
    mask_kernel<<<1, 1024>>>(alphas, gumbel, out + BL);

    conv_split<<<(6 * EE / 4 + 255) / 256, 256>>>(Wqkv, pwh, pwl, 6 * EE / 4);
    conv_split<<<(2 * EE / 4 + 255) / 256, 256>>>(Wo, pwh + 6 * EE, pwl + 6 * EE, 2 * EE / 4);
    conv_split<<<(2 * EE / 4 + 255) / 256, 256>>>(W1, pwh + 8 * EE, pwl + 8 * EE, 2 * EE / 4);
    conv_split<<<(2 * EE / 4 + 255) / 256, 256>>>(W2, pwh + 10 * EE, pwl + 10 * EE, 2 * EE / 4);

    dim3 g512(4, 64);
    dim3 g1024(8, 64);
    dim3 agrid(BATCH * NH, 8);

    for (int l = 0; l < 2; l++) {
        const float* bl = bqkv + (size_t)l * 3 * E;
        size_t wq = (size_t)l * 3 * EE;
        gemm_hmma<<<g512, 256, GEMM_SMEM>>>(pqshh, pqshl, pwh + wq, pwl + wq, bl,
                                            nullptr, pqph, pqpl, 512, 0, 0);
        gemm_hmma<<<g1024, 256, GEMM_SMEM>>>(pxh, pxl, pwh + wq + EE, pwl + wq + EE, bl + E,
                                             nullptr, pkvh, pkvl, 1024, 0, 0);
        attn_hmma<<<agrid, 128, ATT_SMEM>>>(pqph, pqpl, pkvh, pkvl, path, patl);
        gemm_hmma<<<g512, 256, GEMM_SMEM>>>(path, patl, pwh + (6 + l) * EE, pwl + (6 + l) * EE,
                                            bo + l * E, pproj, nullptr, nullptr, 512, 0, 1);
        addln_kernel<<<BL, 128>>>(pqsh, pproj, ln1_s + l * E, ln1_b + l * E, ph, phh, phl);
        gemm_hmma<<<g512, 256, GEMM_SMEM>>>(phh, phl, pwh + (8 + l) * EE, pwl + (8 + l) * EE,
                                            b1 + l * E, nullptr, pf1h, pf1l, 512, 1, 0);
        gemm_hmma<<<g512, 256, GEMM_SMEM>>>(pf1h, pf1l, pwh + (10 + l) * EE, pwl + (10 + l) * EE,
                                            b2 + l * E, pproj, nullptr, nullptr, 512, 0, 1);
        addln_kernel<<<BL, 128>>>(ph, pproj, ln2_s + l * E, ln2_b + l * E, px, pxh, pxl);
    }

    pred_kernel<<<BL, 128>>>(predw, predb, out);
}

// round 7
// speedup vs baseline: 3.4859x; 1.0940x over previous
#include <cuda_runtime.h>
#include <cuda_bf16.h>
#include <math.h>
#include <stdint.h>

#define L 1024
#define BATCH 8
#define E 512
#define NH 8
#define HD 64
#define BL (BATCH * L)
#define NUMC 10000
#define EE (E * E)

// ---------------- scratch (static device globals; no allocation) ----------------
__device__ float g_x[BL * E];
__device__ float g_qsh[BL * E];
__device__ float g_proj[BL * E];
__device__ float g_h[BL * E];
__device__ float g_m[L];

// bf16 hi/lo split buffers
__device__ __nv_bfloat16 g_qshh[BL * E], g_qshl[BL * E];
__device__ __nv_bfloat16 g_xh[BL * E],   g_xl[BL * E];
__device__ __nv_bfloat16 g_hh[BL * E],   g_hl[BL * E];
__device__ __nv_bfloat16 g_qph[BL * E],  g_qpl[BL * E];     // layer-0 q proj
__device__ __nv_bfloat16 g_qp1h[BL * E], g_qp1l[BL * E];    // layer-1 q proj
__device__ __nv_bfloat16 g_kvh[BL * 2 * E], g_kvl[BL * 2 * E];
__device__ __nv_bfloat16 g_atth[BL * E], g_attl[BL * E];
__device__ __nv_bfloat16 g_f1h[BL * E],  g_f1l[BL * E];
__device__ __nv_bfloat16 g_wh[12 * EE],  g_wl[12 * EE];

// ---------------- helpers ----------------
__device__ __forceinline__ float blockSum128(float v, float* sh) {
    int lane = threadIdx.x & 31, w = threadIdx.x >> 5;
    #pragma unroll
    for (int o = 16; o > 0; o >>= 1) v += __shfl_xor_sync(0xffffffffu, v, o);
    if (lane == 0) sh[w] = v;
    __syncthreads();
    float r = sh[0] + sh[1] + sh[2] + sh[3];
    __syncthreads();
    return r;
}

__device__ __forceinline__ uint32_t smem_u32(const void* p) {
    uint32_t a;
    asm("{ .reg .u64 t; cvta.to.shared.u64 t, %1; cvt.u32.u64 %0, t; }" : "=r"(a) : "l"(p));
    return a;
}

__device__ __forceinline__ void split2(float a, float b, uint32_t& hi, uint32_t& lo) {
    __nv_bfloat16 ha = __float2bfloat16_rn(a), hb = __float2bfloat16_rn(b);
    float fa = __bfloat162float(ha), fb = __bfloat162float(hb);
    __nv_bfloat16 la = __float2bfloat16_rn(a - fa), lb = __float2bfloat16_rn(b - fb);
    hi = (uint32_t)__bfloat16_as_ushort(ha) | ((uint32_t)__bfloat16_as_ushort(hb) << 16);
    lo = (uint32_t)__bfloat16_as_ushort(la) | ((uint32_t)__bfloat16_as_ushort(lb) << 16);
}

__device__ __forceinline__ void split4_store(float4 v, __nv_bfloat16* hi, __nv_bfloat16* lo, size_t u2idx) {
    uint2 h, l;
    split2(v.x, v.y, h.x, l.x);
    split2(v.z, v.w, h.y, l.y);
    ((uint2*)hi)[u2idx] = h;
    ((uint2*)lo)[u2idx] = l;
}

// ---------------- embed ----------------
__global__ void embed_kernel(const int* __restrict__ q, const int* __restrict__ r,
                             const int* __restrict__ qry,
                             const float* __restrict__ inter,
                             const float* __restrict__ ex,
                             const float* __restrict__ pos) {
    int t = blockIdx.x;
    int l = t & (L - 1);
    int e4 = threadIdx.x;
    int rowx = q[t] + NUMC * r[t];
    float4 a = ((const float4*)inter)[rowx * (E / 4) + e4];
    float4 p = ((const float4*)pos)[l * (E / 4) + e4];
    float4 xv = make_float4(a.x + p.x, a.y + p.y, a.z + p.z, a.w + p.w);
    float4 qv = ((const float4*)ex)[qry[t] * (E / 4) + e4];
    size_t fi = (size_t)t * 128 + e4;
    ((float4*)g_x)[fi] = xv;
    ((float4*)g_qsh)[fi] = qv;
    split4_store(xv, g_xh, g_xl, fi);
    split4_store(qv, g_qshh, g_qshl, fi);
}

// ---------------- mask ----------------
__global__ void mask_kernel(const float* __restrict__ alphas,
                            const float* __restrict__ gumbel,
                            float* __restrict__ out_l1) {
    int i = threadIdx.x;
    float a0 = alphas[2 * i], a1 = alphas[2 * i + 1];
    float z0 = a0 + gumbel[2 * i], z1 = a1 + gumbel[2 * i + 1];
    g_m[i] = (z0 >= z1) ? 1.0f : 0.0f;
    float v = fabsf(a0) + fabsf(a1);
    __shared__ float sh[32];
    int lane = i & 31, w = i >> 5;
    #pragma unroll
    for (int o = 16; o > 0; o >>= 1) v += __shfl_xor_sync(0xffffffffu, v, o);
    if (lane == 0) sh[w] = v;
    __syncthreads();
    if (i < 32) {
        float x = sh[i];
        #pragma unroll
        for (int o = 16; o > 0; o >>= 1) x += __shfl_xor_sync(0xffffffffu, x, o);
        if (i == 0) out_l1[0] = x;
    }
}

// ---------------- fp32 -> bf16 hi/lo split (weights only) ----------------
__global__ void conv_split(const float* __restrict__ src,
                           __nv_bfloat16* __restrict__ hi,
                           __nv_bfloat16* __restrict__ lo, int n4) {
    int i = blockIdx.x * 256 + threadIdx.x;
    if (i >= n4) return;
    float4 v = ((const float4*)src)[i];
    split4_store(v, hi, lo, i);
}

// ---------------- MMA primitives ----------------
__device__ __forceinline__ void cpasync16(uint32_t dst, const void* src) {
    asm volatile("cp.async.cg.shared.global [%0], [%1], 16;" :: "r"(dst), "l"(src));
}
__device__ __forceinline__ void ldmx4(uint32_t* r, uint32_t addr) {
    asm volatile("ldmatrix.sync.aligned.m8n8.x4.shared.b16 {%0,%1,%2,%3}, [%4];"
                 : "=r"(r[0]), "=r"(r[1]), "=r"(r[2]), "=r"(r[3]) : "r"(addr));
}
__device__ __forceinline__ void ldmx4t(uint32_t* r, uint32_t addr) {
    asm volatile("ldmatrix.sync.aligned.m8n8.x4.trans.shared.b16 {%0,%1,%2,%3}, [%4];"
                 : "=r"(r[0]), "=r"(r[1]), "=r"(r[2]), "=r"(r[3]) : "r"(addr));
}
__device__ __forceinline__ void mma16816(float* d, const uint32_t* a, const uint32_t* b) {
    asm volatile("mma.sync.aligned.m16n8k16.row.col.f32.bf16.bf16.f32 "
                 "{%0,%1,%2,%3}, {%4,%5,%6,%7}, {%8,%9}, {%0,%1,%2,%3};"
                 : "+f"(d[0]), "+f"(d[1]), "+f"(d[2]), "+f"(d[3])
                 : "r"(a[0]), "r"(a[1]), "r"(a[2]), "r"(a[3]), "r"(b[0]), "r"(b[1]));
}

// ---------------- GEMM job descriptor ----------------
struct GJob {
    const __nv_bfloat16 *Ah, *Al, *Bh, *Bl;
    const float* bias;
    float* C;
    __nv_bfloat16 *Chi, *Clo;
    int N, relu, writeC, nbx;
};

// ---------------- HMMA bf16x3 GEMM, 3-stage pipeline, multi-job ----------------
#define GEMM_SMEM (3 * 4 * 16384)
__global__ __launch_bounds__(256, 1)
void gemm_hmma(GJob j0, GJob j1, GJob j2) {
    int bx = blockIdx.x;
    GJob j; int xb;
    if (bx < j0.nbx)                { j = j0; xb = bx; }
    else if (bx < j0.nbx + j1.nbx)  { j = j1; xb = bx - j0.nbx; }
    else                            { j = j2; xb = bx - j0.nbx - j1.nbx; }

    extern __shared__ __align__(1024) char sm[];
    uint32_t sb = smem_u32(sm);
    int t = threadIdx.x;
    int lane = t & 31, warp = t >> 5;
    int m0 = blockIdx.y * 128, n0 = xb * 128;
    int wm = warp & 1, wn = warp >> 1;
    int N = j.N;

    const __nv_bfloat16* srcs[4] = { j.Ah, j.Al, j.Bh, j.Bl };
    int rowbase[4] = { m0, m0, n0, n0 };

    float acc[4][4][4];
    #pragma unroll
    for (int a = 0; a < 4; a++)
        #pragma unroll
        for (int b = 0; b < 4; b++)
            #pragma unroll
            for (int c = 0; c < 4; c++) acc[a][b][c] = 0.f;

    auto load_chunk = [&](int CH, int ST) {
        uint32_t stb = sb + ST * 65536;
        #pragma unroll
        for (int tile = 0; tile < 4; tile++) {
            #pragma unroll
            for (int it = 0; it < 4; it++) {
                int idx = t + it * 256;
                int row = idx >> 3, c16 = idx & 7;
                uint32_t doff = (uint32_t)(row * 128 + ((c16 * 16) ^ ((row & 7) << 4)));
                const __nv_bfloat16* s = srcs[tile] +
                    (size_t)(rowbase[tile] + row) * 512 + CH * 64 + c16 * 8;
                cpasync16(stb + tile * 16384 + doff, s);
            }
        }
        asm volatile("cp.async.commit_group;" ::: "memory");
    };

    load_chunk(0, 0);
    load_chunk(1, 1);

    uint32_t axor = (lane & 7) << 4;
    uint32_t arow = (uint32_t)(wm * 64 + (lane & 15)) * 128;
    uint32_t asel = 16u * ((lane >> 4) & 1);
    uint32_t brow = (uint32_t)(wn * 32 + (lane & 7) + 8 * ((lane >> 4) & 1)) * 128;
    uint32_t bsel = 16u * ((lane >> 3) & 1);

    #pragma unroll
    for (int ch = 0; ch < 8; ch++) {
        if (ch < 7) asm volatile("cp.async.wait_group 1;" ::: "memory");
        else        asm volatile("cp.async.wait_group 0;" ::: "memory");
        __syncthreads();
        if (ch + 2 < 8) load_chunk(ch + 2, (ch + 2) % 3);   // into free stage, before compute
        uint32_t stb = sb + (ch % 3) * 65536;
        uint32_t tAh = stb, tAl = stb + 16384, tBh = stb + 32768, tBl = stb + 49152;
        #pragma unroll
        for (int ks = 0; ks < 4; ks++) {
            uint32_t kb = ks * 32;
            uint32_t ah[4][4], al[4][4], bh[2][4], bl[2][4];
            #pragma unroll
            for (int mf = 0; mf < 4; mf++) {
                uint32_t off = arow + mf * 2048 + ((kb + asel) ^ axor);
                ldmx4(ah[mf], tAh + off);
                ldmx4(al[mf], tAl + off);
            }
            #pragma unroll
            for (int nf16 = 0; nf16 < 2; nf16++) {
                uint32_t off = brow + nf16 * 2048 + ((kb + bsel) ^ axor);
                ldmx4(bh[nf16], tBh + off);
                ldmx4(bl[nf16], tBl + off);
            }
            #pragma unroll
            for (int mf = 0; mf < 4; mf++)
                #pragma unroll
                for (int nf = 0; nf < 4; nf++) {
                    const uint32_t* Bh2 = &bh[nf >> 1][(nf & 1) * 2];
                    const uint32_t* Bl2 = &bl[nf >> 1][(nf & 1) * 2];
                    mma16816(acc[mf][nf], ah[mf], Bh2);
                    mma16816(acc[mf][nf], ah[mf], Bl2);
                    mma16816(acc[mf][nf], al[mf], Bh2);
                }
        }
    }

    int g = lane >> 2, tg = lane & 3;
    #pragma unroll
    for (int mf = 0; mf < 4; mf++) {
        int r0 = m0 + wm * 64 + mf * 16 + g;
        #pragma unroll
        for (int nf = 0; nf < 4; nf++) {
            int c0 = n0 + wn * 32 + nf * 8 + tg * 2;
            float b0 = j.bias[c0], b1 = j.bias[c0 + 1];
            float2 v0 = make_float2(acc[mf][nf][0] + b0, acc[mf][nf][1] + b1);
            float2 v1 = make_float2(acc[mf][nf][2] + b0, acc[mf][nf][3] + b1);
            if (j.relu) {
                v0.x = fmaxf(v0.x, 0.f); v0.y = fmaxf(v0.y, 0.f);
                v1.x = fmaxf(v1.x, 0.f); v1.y = fmaxf(v1.y, 0.f);
            }
            if (j.writeC) {
                *(float2*)(j.C + (size_t)r0 * N + c0) = v0;
                *(float2*)(j.C + (size_t)(r0 + 8) * N + c0) = v1;
            }
            if (j.Chi) {
                uint32_t h0, l0, h1, l1;
                split2(v0.x, v0.y, h0, l0);
                split2(v1.x, v1.y, h1, l1);
                ((uint32_t*)j.Chi)[((size_t)r0 * N + c0) >> 1] = h0;
                ((uint32_t*)j.Clo)[((size_t)r0 * N + c0) >> 1] = l0;
                ((uint32_t*)j.Chi)[((size_t)(r0 + 8) * N + c0) >> 1] = h1;
                ((uint32_t*)j.Clo)[((size_t)(r0 + 8) * N + c0) >> 1] = l1;
            }
        }
    }
}

// ---------------- HMMA flash attention, bf16x3, masked causal, cp.async KV ----------------
// grid (B*NH, 8), block 128 (4 warps x 32 q-rows). K-tiles of 32 keys, double-buffered.
#define ATT_SMEM (32768 + 2 * 16384 + 4096)
__global__ __launch_bounds__(128, 1)
void attn_hmma(const __nv_bfloat16* __restrict__ Qh, const __nv_bfloat16* __restrict__ Ql,
               const __nv_bfloat16* __restrict__ KVh, const __nv_bfloat16* __restrict__ KVl,
               __nv_bfloat16* __restrict__ Oh, __nv_bfloat16* __restrict__ Ol) {
    extern __shared__ __align__(128) char sm[];
    const uint32_t oQh = 0, oQl = 16384, oKV = 32768;  // per-stage: Kh 0, Kl 4096, Vh 8192, Vl 12288
    float* biasS = (float*)(sm + 65536);
    uint32_t sb = smem_u32(sm);
    int t = threadIdx.x, lane = t & 31, warp = t >> 5;
    int b = blockIdx.x >> 3, h = blockIdx.x & 7;
    int qb = blockIdx.y, qbase = qb * 128;
    int ntiles = (qb + 1) * 4;

    auto load_kv = [&](int tile, int st) {
        int j0 = tile * 32;
        uint32_t stb = sb + oKV + st * 16384;
        #pragma unroll
        for (int it = 0; it < 2; it++) {
            int idx = t + it * 128;
            int row = idx >> 3, c = idx & 7;
            size_t koff = (size_t)(b * L + j0 + row) * 1024 + h * 64 + c * 8;
            uint32_t doff = (uint32_t)(row * 128 + ((c ^ (row & 7)) << 4));
            cpasync16(stb + doff,         KVh + koff);
            cpasync16(stb + 4096 + doff,  KVl + koff);
            cpasync16(stb + 8192 + doff,  KVh + koff + 512);
            cpasync16(stb + 12288 + doff, KVl + koff + 512);
        }
        asm volatile("cp.async.commit_group;" ::: "memory");
    };

    load_kv(0, 0);
    load_kv(1, 1);

    for (int k = t; k < 1024; k += 128) biasS[k] = (g_m[k] != 0.f) ? 0.f : -1e30f;

    // stage Q hi/lo (128 rows x 64 halves, swizzled)
    #pragma unroll
    for (int it = 0; it < 8; it++) {
        int idx = t + it * 128;
        int row = idx >> 3, c = idx & 7;
        size_t goff = (size_t)(b * L + qbase + row) * 512 + h * 64 + c * 8;
        uint32_t doff = (uint32_t)(row * 128 + ((c ^ (row & 7)) << 4));
        *(uint4*)(sm + oQh + doff) = *(const uint4*)(Qh + goff);
        *(uint4*)(sm + oQl + doff) = *(const uint4*)(Ql + goff);
    }
    __syncthreads();

    uint32_t qfh[2][4][4];
    #pragma unroll
    for (int mf = 0; mf < 2; mf++)
        #pragma unroll
        for (int kk = 0; kk < 4; kk++) {
            int r = warp * 32 + mf * 16 + (lane & 15);
            int hb = kk * 2 + ((lane >> 4) & 1);
            ldmx4(qfh[mf][kk], sb + oQh + r * 128 + ((hb ^ (r & 7)) << 4));
        }

    float Ow[2][8][4];
    #pragma unroll
    for (int a = 0; a < 2; a++)
        #pragma unroll
        for (int bb = 0; bb < 8; bb++)
            #pragma unroll
            for (int c = 0; c < 4; c++) Ow[a][bb][c] = 0.f;
    float mx[2][2] = {{-1e4f, -1e4f}, {-1e4f, -1e4f}};
    float sums[2][2] = {{0.f, 0.f}, {0.f, 0.f}};
    int g = lane >> 2, tq = lane & 3;

    for (int tile = 0; tile < ntiles; tile++) {
        int j0 = tile * 32;
        if (tile < ntiles - 1) asm volatile("cp.async.wait_group 1;" ::: "memory");
        else                   asm volatile("cp.async.wait_group 0;" ::: "memory");
        __syncthreads();
        uint32_t stb = sb + oKV + (tile & 1) * 16384;
        uint32_t tKh = stb, tKl = stb + 4096, tVh = stb + 8192, tVl = stb + 12288;

        // S = Q K^T (bf16x3)
        float S[2][4][4];
        #pragma unroll
        for (int a = 0; a < 2; a++)
            #pragma unroll
            for (int bb = 0; bb < 4; bb++)
                #pragma unroll
                for (int c = 0; c < 4; c++) S[a][bb][c] = 0.f;

        #pragma unroll
        for (int kk = 0; kk < 4; kk++) {
            uint32_t qfl[2][4];
            #pragma unroll
            for (int mf = 0; mf < 2; mf++) {
                int r = warp * 32 + mf * 16 + (lane & 15);
                int hb = kk * 2 + ((lane >> 4) & 1);
                ldmx4(qfl[mf], sb + oQl + r * 128 + ((hb ^ (r & 7)) << 4));
            }
            #pragma unroll
            for (int pair = 0; pair < 2; pair++) {
                int kr = (pair * 2 + ((lane >> 4) & 1)) * 8 + (lane & 7);
                int hb = kk * 2 + ((lane >> 3) & 1);
                uint32_t off = (uint32_t)(kr * 128 + ((hb ^ (kr & 7)) << 4));
                uint32_t kh4[4], kl4[4];
                ldmx4(kh4, tKh + off);
                ldmx4(kl4, tKl + off);
                #pragma unroll
                for (int sub = 0; sub < 2; sub++) {
                    int ng = pair * 2 + sub;
                    #pragma unroll
                    for (int mf = 0; mf < 2; mf++) {
                        mma16816(S[mf][ng], qfh[mf][kk], kh4 + sub * 2);
                        mma16816(S[mf][ng], qfh[mf][kk], kl4 + sub * 2);
                        mma16816(S[mf][ng], qfl[mf],     kh4 + sub * 2);
                    }
                }
            }
        }

        // masked online softmax + P fragment build
        uint32_t Ph[2][2][4], Pl[2][2][4];
        #pragma unroll
        for (int mf = 0; mf < 2; mf++) {
            int i0 = qbase + warp * 32 + mf * 16 + g;
            int i1 = i0 + 8;
            float r0 = -1e30f, r1 = -1e30f;
            #pragma unroll
            for (int ng = 0; ng < 4; ng++)
                #pragma unroll
                for (int e = 0; e < 2; e++) {
                    int jj = j0 + ng * 8 + tq * 2 + e;
                    float s0 = (jj <= i0) ? S[mf][ng][e] * 0.125f + biasS[i0 - jj] : -1e30f;
                    float s1 = (jj <= i1) ? S[mf][ng][2 + e] * 0.125f + biasS[i1 - jj] : -1e30f;
                    S[mf][ng][e] = s0; S[mf][ng][2 + e] = s1;
                    r0 = fmaxf(r0, s0); r1 = fmaxf(r1, s1);
                }
            r0 = fmaxf(r0, __shfl_xor_sync(0xffffffffu, r0, 1));
            r0 = fmaxf(r0, __shfl_xor_sync(0xffffffffu, r0, 2));
            r1 = fmaxf(r1, __shfl_xor_sync(0xffffffffu, r1, 1));
            r1 = fmaxf(r1, __shfl_xor_sync(0xffffffffu, r1, 2));
            float mN0 = fmaxf(mx[mf][0], r0), mN1 = fmaxf(mx[mf][1], r1);
            float f0 = __expf(mx[mf][0] - mN0), f1 = __expf(mx[mf][1] - mN1);
            mx[mf][0] = mN0; mx[mf][1] = mN1;
            float ps0 = 0.f, ps1 = 0.f;
            #pragma unroll
            for (int ng = 0; ng < 4; ng++)
                #pragma unroll
                for (int e = 0; e < 2; e++) {
                    float p0 = __expf(S[mf][ng][e] - mN0);
                    float p1 = __expf(S[mf][ng][2 + e] - mN1);
                    S[mf][ng][e] = p0; S[mf][ng][2 + e] = p1;
                    ps0 += p0; ps1 += p1;
                }
            ps0 += __shfl_xor_sync(0xffffffffu, ps0, 1);
            ps0 += __shfl_xor_sync(0xffffffffu, ps0, 2);
            ps1 += __shfl_xor_sync(0xffffffffu, ps1, 1);
            ps1 += __shfl_xor_sync(0xffffffffu, ps1, 2);
            sums[mf][0] = sums[mf][0] * f0 + ps0;
            sums[mf][1] = sums[mf][1] * f1 + ps1;
            #pragma unroll
            for (int nf = 0; nf < 8; nf++) {
                Ow[mf][nf][0] *= f0; Ow[mf][nf][1] *= f0;
                Ow[mf][nf][2] *= f1; Ow[mf][nf][3] *= f1;
            }
            #pragma unroll
            for (int kb = 0; kb < 2; kb++) {
                split2(S[mf][2 * kb][0],     S[mf][2 * kb][1],     Ph[mf][kb][0], Pl[mf][kb][0]);
                split2(S[mf][2 * kb][2],     S[mf][2 * kb][3],     Ph[mf][kb][1], Pl[mf][kb][1]);
                split2(S[mf][2 * kb + 1][0], S[mf][2 * kb + 1][1], Ph[mf][kb][2], Pl[mf][kb][2]);
                split2(S[mf][2 * kb + 1][2], S[mf][2 * kb + 1][3], Ph[mf][kb][3], Pl[mf][kb][3]);
            }
        }

        // O += P V (bf16x3)
        #pragma unroll
        for (int kb = 0; kb < 2; kb++)
            #pragma unroll
            for (int pair = 0; pair < 4; pair++) {
                int kr = kb * 16 + ((lane >> 3) & 1) * 8 + (lane & 7);
                int hb = pair * 2 + ((lane >> 4) & 1);
                uint32_t off = (uint32_t)(kr * 128 + ((hb ^ (kr & 7)) << 4));
                uint32_t vh4[4], vl4[4];
                ldmx4t(vh4, tVh + off);
                ldmx4t(vl4, tVl + off);
                #pragma unroll
                for (int sub = 0; sub < 2; sub++) {
                    int nf = pair * 2 + sub;
                    #pragma unroll
                    for (int mf = 0; mf < 2; mf++) {
                        mma16816(Ow[mf][nf], Ph[mf][kb], vh4 + sub * 2);
                        mma16816(Ow[mf][nf], Ph[mf][kb], vl4 + sub * 2);
                        mma16816(Ow[mf][nf], Pl[mf][kb], vh4 + sub * 2);
                    }
                }
            }

        if (tile + 2 < ntiles) {
            __syncthreads();
            load_kv(tile + 2, tile & 1);
        }
    }

    // epilogue
    #pragma unroll
    for (int mf = 0; mf < 2; mf++) {
        float inv0 = 1.f / sums[mf][0], inv1 = 1.f / sums[mf][1];
        int i0 = qbase + warp * 32 + mf * 16 + g;
        int i1 = i0 + 8;
        #pragma unroll
        for (int nf = 0; nf < 8; nf++) {
            int cc = h * 64 + nf * 8 + tq * 2;
            uint32_t h0, l0, h1, l1;
            split2(Ow[mf][nf][0] * inv0, Ow[mf][nf][1] * inv0, h0, l0);
            split2(Ow[mf][nf][2] * inv1, Ow[mf][nf][3] * inv1, h1, l1);
            ((uint32_t*)Oh)[((size_t)(b * L + i0) * 512 + cc) >> 1] = h0;
            ((uint32_t*)Ol)[((size_t)(b * L + i0) * 512 + cc) >> 1] = l0;
            ((uint32_t*)Oh)[((size_t)(b * L + i1) * 512 + cc) >> 1] = h1;
            ((uint32_t*)Ol)[((size_t)(b * L + i1) * 512 + cc) >> 1] = l1;
        }
    }
}

// ---------------- out = LayerNorm(a + b) * s + bb  (+ bf16 split) ----------------
__global__ void addln_kernel(const float* __restrict__ a, const float* __restrict__ b,
                             const float* __restrict__ s, const float* __restrict__ bb,
                             float* __restrict__ out,
                             __nv_bfloat16* __restrict__ outh, __nv_bfloat16* __restrict__ outl) {
    int tkn = blockIdx.x;
    int t = threadIdx.x;
    __shared__ float sh[4];
    float4 av = ((const float4*)a)[tkn * 128 + t];
    float4 bv = ((const float4*)b)[tkn * 128 + t];
    float4 v = make_float4(av.x + bv.x, av.y + bv.y, av.z + bv.z, av.w + bv.w);
    float total = blockSum128(v.x + v.y + v.z + v.w, sh);
    float mean = total * (1.f / 512.f);
    float dx = v.x - mean, dy = v.y - mean, dz = v.z - mean, dw = v.w - mean;
    float vtot = blockSum128(dx * dx + dy * dy + dz * dz + dw * dw, sh);
    float inv = rsqrtf(vtot * (1.f / 512.f) + 1e-5f);
    float4 sv = ((const float4*)s)[t];
    float4 bv2 = ((const float4*)bb)[t];
    float4 o = make_float4(dx * inv * sv.x + bv2.x, dy * inv * sv.y + bv2.y,
                           dz * inv * sv.z + bv2.z, dw * inv * sv.w + bv2.w);
    size_t fi = (size_t)tkn * 128 + t;
    ((float4*)out)[fi] = o;
    split4_store(o, outh, outl, fi);
}

// ---------------- p = sigmoid(x . w + b) ----------------
__global__ void pred_kernel(const float* __restrict__ w, const float* __restrict__ pb,
                            float* __restrict__ out) {
    int tkn = blockIdx.x;
    int t = threadIdx.x;
    __shared__ float sh[4];
    float4 xv = ((const float4*)g_x)[tkn * 128 + t];
    float4 wv = ((const float4*)w)[t];
    float local = xv.x * wv.x + xv.y * wv.y + xv.z * wv.z + xv.w * wv.w;
    float z = blockSum128(local, sh) + pb[0];
    if (t == 0) out[tkn] = 1.f / (1.f + __expf(-z));
}

// ---------------- launch ----------------
extern "C" void kernel_launch(void* const* d_in, const int* in_sizes, int n_in,
                              void* d_out, int out_size) {
    const int*   q      = (const int*)d_in[0];
    const int*   r      = (const int*)d_in[1];
    const int*   qry    = (const int*)d_in[2];
    const float* alphas = (const float*)d_in[3];
    const float* gumbel = (const float*)d_in[4];
    const float* inter  = (const float*)d_in[5];
    const float* ex     = (const float*)d_in[6];
    const float* pos    = (const float*)d_in[7];
    const float* Wqkv   = (const float*)d_in[8];
    const float* bqkv   = (const float*)d_in[9];
    const float* Wo     = (const float*)d_in[10];
    const float* bo     = (const float*)d_in[11];
    const float* ln1_s  = (const float*)d_in[12];
    const float* ln1_b  = (const float*)d_in[13];
    const float* W1     = (const float*)d_in[14];
    const float* b1     = (const float*)d_in[15];
    const float* W2     = (const float*)d_in[16];
    const float* b2     = (const float*)d_in[17];
    const float* ln2_s  = (const float*)d_in[18];
    const float* ln2_b  = (const float*)d_in[19];
    const float* predw  = (const float*)d_in[20];
    const float* predb  = (const float*)d_in[21];
    float* out = (float*)d_out;

    cudaFuncSetAttribute(gemm_hmma, cudaFuncAttributeMaxDynamicSharedMemorySize, GEMM_SMEM);
    cudaFuncSetAttribute(attn_hmma, cudaFuncAttributeMaxDynamicSharedMemorySize, ATT_SMEM);

    float *px, *pqsh, *pproj, *ph;
    cudaGetSymbolAddress((void**)&px, g_x);
    cudaGetSymbolAddress((void**)&pqsh, g_qsh);
    cudaGetSymbolAddress((void**)&pproj, g_proj);
    cudaGetSymbolAddress((void**)&ph, g_h);
    __nv_bfloat16 *pqshh, *pqshl, *pxh, *pxl, *phh, *phl, *pqph, *pqpl, *pq1h, *pq1l,
                  *pkvh, *pkvl, *path, *patl, *pf1h, *pf1l, *pwh, *pwl;
    cudaGetSymbolAddress((void**)&pqshh, g_qshh); cudaGetSymbolAddress((void**)&pqshl, g_qshl);
    cudaGetSymbolAddress((void**)&pxh, g_xh);     cudaGetSymbolAddress((void**)&pxl, g_xl);
    cudaGetSymbolAddress((void**)&phh, g_hh);     cudaGetSymbolAddress((void**)&phl, g_hl);
    cudaGetSymbolAddress((void**)&pqph, g_qph);   cudaGetSymbolAddress((void**)&pqpl, g_qpl);
    cudaGetSymbolAddress((void**)&pq1h, g_qp1h);  cudaGetSymbolAddress((void**)&pq1l, g_qp1l);
    cudaGetSymbolAddress((void**)&pkvh, g_kvh);   cudaGetSymbolAddress((void**)&pkvl, g_kvl);
    cudaGetSymbolAddress((void**)&path, g_atth);  cudaGetSymbolAddress((void**)&patl, g_attl);
    cudaGetSymbolAddress((void**)&pf1h, g_f1h);   cudaGetSymbolAddress((void**)&pf1l, g_f1l);
    cudaGetSymbolAddress((void**)&pwh, g_wh);     cudaGetSymbolAddress((void**)&pwl, g_wl);

    embed_kernel<<<BL, 128>>>(q, r, qry, inter, ex, pos);
    mask_kernel<<<1, 1024>>>(alphas, gumbel, out + BL);

    conv_split<<<(6 * EE / 4 + 255) / 256, 256>>>(Wqkv, pwh, pwl, 6 * EE / 4);
    conv_split<<<(2 * EE / 4 + 255) / 256, 256>>>(Wo, pwh + 6 * EE, pwl + 6 * EE, 2 * EE / 4);
    conv_split<<<(2 * EE / 4 + 255) / 256, 256>>>(W1, pwh + 8 * EE, pwl + 8 * EE, 2 * EE / 4);
    conv_split<<<(2 * EE / 4 + 255) / 256, 256>>>(W2, pwh + 10 * EE, pwl + 10 * EE, 2 * EE / 4);

    GJob z = {};   // nbx = 0
    auto launch1 = [&](GJob j) {
        j.nbx = j.N / 128;
        dim3 grid(j.nbx, 64);
        gemm_hmma<<<grid, 256, GEMM_SMEM>>>(j, z, z);
    };

    dim3 agrid(BATCH * NH, 8);

    // merged head-of-chain launch: Q-proj layer0, Q-proj layer1, KV-proj layer0
    {
        GJob jq0 = { pqshh, pqshl, pwh,         pwl,         bqkv,           nullptr, pqph, pqpl, 512, 0, 0, 4 };
        GJob jq1 = { pqshh, pqshl, pwh + 3 * EE, pwl + 3 * EE, bqkv + 3 * E,  nullptr, pq1h, pq1l, 512, 0, 0, 4 };
        GJob jkv = { pxh,   pxl,   pwh + EE,    pwl + EE,    bqkv + E,       nullptr, pkvh, pkvl, 1024, 0, 0, 8 };
        dim3 grid(16, 64);
        gemm_hmma<<<grid, 256, GEMM_SMEM>>>(jq0, jq1, jkv);
    }

    for (int l = 0; l < 2; l++) {
        const float* bl = bqkv + (size_t)l * 3 * E;
        size_t wq = (size_t)l * 3 * EE;
        if (l == 1) {  // KV for layer 1 (Q already done)
            launch1({ pxh, pxl, pwh + wq + EE, pwl + wq + EE, bl + E, nullptr, pkvh, pkvl, 1024, 0, 0, 0 });
        }
        const __nv_bfloat16* Qh = (l == 0) ? pqph : pq1h;
        const __nv_bfloat16* Ql = (l == 0) ? pqpl : pq1l;
        attn_hmma<<<agrid, 128, ATT_SMEM>>>(Qh, Ql, pkvh, pkvl, path, patl);
        launch1({ path, patl, pwh + (6 + l) * EE, pwl + (6 + l) * EE, bo + l * E, pproj, nullptr, nullptr, 512, 0, 1, 0 });
        addln_kernel<<<BL, 128>>>(pqsh, pproj, ln1_s + l * E, ln1_b + l * E, ph, phh, phl);
        launch1({ phh, phl, pwh + (8 + l) * EE, pwl + (8 + l) * EE, b1 + l * E, nullptr, pf1h, pf1l, 512, 1, 0, 0 });
        launch1({ pf1h, pf1l, pwh + (10 + l) * EE, pwl + (10 + l) * EE, b2 + l * E, pproj, nullptr, nullptr, 512, 0, 1, 0 });
        addln_kernel<<<BL, 128>>>(ph, pproj, ln2_s + l * E, ln2_b + l * E, px, pxh, pxl);
    }

    pred_kernel<<<BL, 128>>>(predw, predb, out);
}